// round 9
// baseline (speedup 1.0000x reference)
#include <cuda_runtime.h>
#include <cstdint>

#define N_NODES 100000
#define N_EDGES 600000
#define IN_C    128
#define OUT_C   128
#define M_TILE  128
#define N_TILES ((N_NODES + M_TILE - 1) / M_TILE)   // 782
#define M_PAD   (N_TILES * M_TILE)                  // 100096
#define KCH     32
#define NCHUNK  (IN_C / KCH)                        // 4
#define A_STRIDE 132                                 // full-K A tile row stride
#define BS_STRIDE 136
#define A_BUF   (M_TILE * A_STRIDE)                  // 16896 floats
#define B_BUF   (KCH * BS_STRIDE)                    // 4352 floats
#define SMEM_BYTES ((A_BUF + 2 * B_BUF) * 4)         // 102400

#define NB      (3 * N_NODES)                        // 300000 buckets
#define SCAN_BS 2048
#define SCAN_BLOCKS ((NB + SCAN_BS - 1) / SCAN_BS)   // 147

// h[r][M_PAD][128]
__device__ float g_h[(size_t)3 * M_PAD * OUT_C];
// CSR infrastructure
__device__ int g_cnt[NB];
__device__ int g_rowstart[NB + 1];
__device__ int g_cursor[NB];
__device__ int g_sorted[3 * N_EDGES];
__device__ int g_partial[SCAN_BLOCKS];

static __device__ __forceinline__ uint32_t tf32_rna(float x) {
    uint32_t y;
    asm("cvt.rna.tf32.f32 %0, %1;" : "=r"(y) : "f"(x));
    return y;
}

// ---------------------------------------------------------------------------
// 1) GEMM: h_j = x @ W_j. Full A tile staged ONCE, 3 relations looped inside.
// ---------------------------------------------------------------------------
__global__ __launch_bounds__(256, 2) void gemm_hmma_kernel(
        const float4* __restrict__ x4,
        const float* __restrict__ W0,
        const float* __restrict__ W1,
        const float* __restrict__ W2) {
    extern __shared__ float smem[];
    float* A  = smem;
    float* Bs[2] = { smem + A_BUF, smem + A_BUF + B_BUF };

    int tid  = threadIdx.x;
    int lane = tid & 31;
    int wid  = tid >> 5;
    int wr   = wid >> 2;
    int wc   = wid & 3;
    int g    = lane >> 2;
    int tg   = lane & 3;

    int tile_row0 = blockIdx.x * M_TILE;

    #pragma unroll
    for (int i = tid; i < 4096; i += 256) {
        int row = i >> 5, c4 = i & 31;
        int srow = tile_row0 + row;
        if (srow >= N_NODES) srow = 0;               // pad rows: any value
        float4 v = __ldg(x4 + (size_t)srow * (IN_C / 4) + c4);
        uint32_t* p = reinterpret_cast<uint32_t*>(A + row * A_STRIDE + c4 * 4);
        p[0] = tf32_rna(v.x); p[1] = tf32_rna(v.y);
        p[2] = tf32_rna(v.z); p[3] = tf32_rna(v.w);
    }
    __syncthreads();

    const uint32_t* Au = reinterpret_cast<const uint32_t*>(A);

    for (int rel = 0; rel < 3; rel++) {
        const float* Wj = (rel == 0) ? W0 : (rel == 1 ? W1 : W2);
        float* hj = g_h + (size_t)rel * M_PAD * OUT_C;

        auto stageB = [&](int c, int b) {
            float* B = Bs[b];
            #pragma unroll
            for (int i = tid; i < 1024; i += 256) {
                int k = i >> 5, n4 = i & 31;
                float4 v = __ldg(reinterpret_cast<const float4*>(
                                 Wj + (size_t)(c * KCH + k) * OUT_C) + n4);
                uint32_t* p = reinterpret_cast<uint32_t*>(B + k * BS_STRIDE + n4 * 4);
                p[0] = tf32_rna(v.x); p[1] = tf32_rna(v.y);
                p[2] = tf32_rna(v.z); p[3] = tf32_rna(v.w);
            }
        };

        float acc[4][4][4];
        #pragma unroll
        for (int mt = 0; mt < 4; mt++)
            #pragma unroll
            for (int nt = 0; nt < 4; nt++)
                #pragma unroll
                for (int r = 0; r < 4; r++) acc[mt][nt][r] = 0.f;

        stageB(0, 0);
        __syncthreads();

        for (int c = 0; c < NCHUNK; c++) {
            int b = c & 1;
            if (c + 1 < NCHUNK) stageB(c + 1, b ^ 1);

            const uint32_t* B = reinterpret_cast<const uint32_t*>(Bs[b]);

            #pragma unroll
            for (int ks = 0; ks < KCH / 8; ks++) {
                int kk = c * KCH + ks * 8;
                int kb = ks * 8;
                uint32_t af[4][4], bf[4][2];
                #pragma unroll
                for (int mt = 0; mt < 4; mt++) {
                    int m0 = wr * 64 + mt * 16 + g;
                    af[mt][0] = Au[(m0)     * A_STRIDE + kk + tg];
                    af[mt][1] = Au[(m0 + 8) * A_STRIDE + kk + tg];
                    af[mt][2] = Au[(m0)     * A_STRIDE + kk + tg + 4];
                    af[mt][3] = Au[(m0 + 8) * A_STRIDE + kk + tg + 4];
                }
                #pragma unroll
                for (int nt = 0; nt < 4; nt++) {
                    int n0 = wc * 32 + nt * 8 + g;
                    bf[nt][0] = B[(kb + tg)     * BS_STRIDE + n0];
                    bf[nt][1] = B[(kb + tg + 4) * BS_STRIDE + n0];
                }
                #pragma unroll
                for (int mt = 0; mt < 4; mt++)
                    #pragma unroll
                    for (int nt = 0; nt < 4; nt++) {
                        asm volatile(
                            "mma.sync.aligned.m16n8k8.row.col.f32.tf32.tf32.f32 "
                            "{%0,%1,%2,%3}, {%4,%5,%6,%7}, {%8,%9}, {%0,%1,%2,%3};"
                            : "+f"(acc[mt][nt][0]), "+f"(acc[mt][nt][1]),
                              "+f"(acc[mt][nt][2]), "+f"(acc[mt][nt][3])
                            : "r"(af[mt][0]), "r"(af[mt][1]),
                              "r"(af[mt][2]), "r"(af[mt][3]),
                              "r"(bf[nt][0]), "r"(bf[nt][1]));
                    }
            }
            __syncthreads();
        }

        #pragma unroll
        for (int mt = 0; mt < 4; mt++) {
            int row = tile_row0 + wr * 64 + mt * 16 + g;
            #pragma unroll
            for (int nt = 0; nt < 4; nt++) {
                int col = wc * 32 + nt * 8 + 2 * tg;
                float2* p0 = reinterpret_cast<float2*>(hj + (size_t)row * OUT_C + col);
                float2* p1 = reinterpret_cast<float2*>(hj + (size_t)(row + 8) * OUT_C + col);
                *p0 = make_float2(acc[mt][nt][0], acc[mt][nt][1]);
                *p1 = make_float2(acc[mt][nt][2], acc[mt][nt][3]);
            }
        }
    }
}

// ---------------------------------------------------------------------------
// CSR build
// ---------------------------------------------------------------------------
__global__ void zero_cnt_kernel() {
    int i = blockIdx.x * blockDim.x + threadIdx.x;
    if (i < NB) g_cnt[i] = 0;
}

__global__ void count_kernel(const int* __restrict__ d0,
                             const int* __restrict__ d1,
                             const int* __restrict__ d2) {
    unsigned gid = blockIdx.x * blockDim.x + threadIdx.x;
    if (gid >= 3u * N_EDGES) return;
    int rel, e;
    const int* dp;
    if (gid < (unsigned)N_EDGES)          { rel = 0; e = gid;                dp = d0; }
    else if (gid < 2u * (unsigned)N_EDGES){ rel = 1; e = gid - N_EDGES;      dp = d1; }
    else                                  { rel = 2; e = gid - 2u * N_EDGES; dp = d2; }
    atomicAdd(&g_cnt[rel * N_NODES + __ldg(dp + e)], 1);
}

__global__ void scan_a_kernel() {      // per-block totals
    __shared__ int sb[256];
    int t = threadIdx.x;
    int base = blockIdx.x * SCAN_BS + t * 8;
    int sum = 0;
    #pragma unroll
    for (int j = 0; j < 8; j++) {
        int idx = base + j;
        if (idx < NB) sum += g_cnt[idx];
    }
    sb[t] = sum;
    __syncthreads();
    for (int off = 128; off > 0; off >>= 1) {
        if (t < off) sb[t] += sb[t + off];
        __syncthreads();
    }
    if (t == 0) g_partial[blockIdx.x] = sb[0];
}

__global__ void scan_b_kernel() {      // parallel exclusive scan of partials
    __shared__ int sb[256];
    int t = threadIdx.x;
    int v = (t < SCAN_BLOCKS) ? g_partial[t] : 0;
    sb[t] = v;
    __syncthreads();
    for (int off = 1; off < 256; off <<= 1) {
        int add = (t >= off) ? sb[t - off] : 0;
        __syncthreads();
        sb[t] += add;
        __syncthreads();
    }
    if (t < SCAN_BLOCKS) g_partial[t] = sb[t] - v;   // exclusive
    if (t == 255) g_rowstart[NB] = sb[255];          // total
}

__global__ void scan_c_kernel() {
    __shared__ int sb[256];
    int t = threadIdx.x;
    int base = blockIdx.x * SCAN_BS + t * 8;
    int v[8];
    int tsum = 0;
    #pragma unroll
    for (int j = 0; j < 8; j++) {
        int idx = base + j;
        v[j] = (idx < NB) ? g_cnt[idx] : 0;
        tsum += v[j];
    }
    sb[t] = tsum;
    __syncthreads();
    for (int off = 1; off < 256; off <<= 1) {
        int add = (t >= off) ? sb[t - off] : 0;
        __syncthreads();
        sb[t] += add;
        __syncthreads();
    }
    int run = g_partial[blockIdx.x] + sb[t] - tsum;
    #pragma unroll
    for (int j = 0; j < 8; j++) {
        int idx = base + j;
        if (idx < NB) {
            g_rowstart[idx] = run;
            g_cursor[idx] = run;
            run += v[j];
        }
    }
}

__global__ void fill_kernel(const int* __restrict__ s0, const int* __restrict__ d0,
                            const int* __restrict__ s1, const int* __restrict__ d1,
                            const int* __restrict__ s2, const int* __restrict__ d2) {
    unsigned gid = blockIdx.x * blockDim.x + threadIdx.x;
    if (gid >= 3u * N_EDGES) return;
    int rel, e;
    const int* sp;
    const int* dp;
    if (gid < (unsigned)N_EDGES)          { rel = 0; e = gid;                sp = s0; dp = d0; }
    else if (gid < 2u * (unsigned)N_EDGES){ rel = 1; e = gid - N_EDGES;      sp = s1; dp = d1; }
    else                                  { rel = 2; e = gid - 2u * N_EDGES; sp = s2; dp = d2; }
    int d = __ldg(dp + e);
    int pos = atomicAdd(&g_cursor[rel * N_NODES + d], 1);
    g_sorted[pos] = __ldg(sp + e);
}

// ---------------------------------------------------------------------------
// Gather, ONE relation per launch (h_rel + out stay L2-resident).
// mode bit0 = accumulate into existing out, bit1 = apply relu at the end.
// One warp per node, 4-wide unrolled row walk (MLP 4).
// ---------------------------------------------------------------------------
__global__ void gather_rel_kernel(float4* __restrict__ out4, int rel, int mode) {
    unsigned n    = (blockIdx.x * blockDim.x + threadIdx.x) >> 5;
    int      lane = threadIdx.x & 31;
    if (n >= (unsigned)N_NODES) return;

    int idx = rel * N_NODES + (int)n;
    int e   = __ldg(&g_rowstart[idx]);
    int end = __ldg(&g_rowstart[idx + 1]);
    const float4* h4 = reinterpret_cast<const float4*>(
        g_h + (size_t)rel * M_PAD * OUT_C);

    float4 acc = make_float4(0.f, 0.f, 0.f, 0.f);

    for (; e + 3 < end; e += 4) {
        int s0 = __ldg(&g_sorted[e]);
        int s1 = __ldg(&g_sorted[e + 1]);
        int s2 = __ldg(&g_sorted[e + 2]);
        int s3 = __ldg(&g_sorted[e + 3]);
        float4 v0 = __ldg(h4 + (size_t)s0 * (OUT_C / 4) + lane);
        float4 v1 = __ldg(h4 + (size_t)s1 * (OUT_C / 4) + lane);
        float4 v2 = __ldg(h4 + (size_t)s2 * (OUT_C / 4) + lane);
        float4 v3 = __ldg(h4 + (size_t)s3 * (OUT_C / 4) + lane);
        acc.x += (v0.x + v1.x) + (v2.x + v3.x);
        acc.y += (v0.y + v1.y) + (v2.y + v3.y);
        acc.z += (v0.z + v1.z) + (v2.z + v3.z);
        acc.w += (v0.w + v1.w) + (v2.w + v3.w);
    }
    for (; e < end; e++) {
        int s0 = __ldg(&g_sorted[e]);
        float4 v0 = __ldg(h4 + (size_t)s0 * (OUT_C / 4) + lane);
        acc.x += v0.x; acc.y += v0.y; acc.z += v0.z; acc.w += v0.w;
    }

    float4* po = out4 + (size_t)n * (OUT_C / 4) + lane;
    if (mode & 1) {
        float4 prev = *po;
        acc.x += prev.x; acc.y += prev.y; acc.z += prev.z; acc.w += prev.w;
    }
    if (mode & 2) {
        acc.x = fmaxf(acc.x, 0.f); acc.y = fmaxf(acc.y, 0.f);
        acc.z = fmaxf(acc.z, 0.f); acc.w = fmaxf(acc.w, 0.f);
    }
    *po = acc;
}

// ---------------------------------------------------------------------------
// launch
// ---------------------------------------------------------------------------
extern "C" void kernel_launch(void* const* d_in, const int* in_sizes, int n_in,
                              void* d_out, int out_size) {
    const float* x  = (const float*)d_in[0];
    const float* W0 = (const float*)d_in[1];
    const float* W1 = (const float*)d_in[2];
    const float* W2 = (const float*)d_in[3];
    const int* s0 = (const int*)d_in[4];
    const int* d0 = (const int*)d_in[5];
    const int* s1 = (const int*)d_in[6];
    const int* d1 = (const int*)d_in[7];
    const int* s2 = (const int*)d_in[8];
    const int* d2 = (const int*)d_in[9];
    float* out = (float*)d_out;

    // CSR build
    zero_cnt_kernel<<<(NB + 255) / 256, 256>>>();
    count_kernel<<<(3 * N_EDGES + 255) / 256, 256>>>(d0, d1, d2);
    scan_a_kernel<<<SCAN_BLOCKS, 256>>>();
    scan_b_kernel<<<1, 256>>>();
    scan_c_kernel<<<SCAN_BLOCKS, 256>>>();
    fill_kernel<<<(3 * N_EDGES + 255) / 256, 256>>>(s0, d0, s1, d1, s2, d2);

    // GEMM: h_r = x @ W_r
    {
        static bool attr_set = false;   // idempotent attribute set
        if (!attr_set) {
            cudaFuncSetAttribute(gemm_hmma_kernel,
                                 cudaFuncAttributeMaxDynamicSharedMemorySize,
                                 SMEM_BYTES);
            attr_set = true;
        }
        gemm_hmma_kernel<<<N_TILES, 256, SMEM_BYTES>>>(
            reinterpret_cast<const float4*>(x), W0, W1, W2);
    }

    // Gather, one relation per launch: store / add / add+relu
    {
        long long threads = (long long)N_NODES * 32;
        int blocks = (int)((threads + 255) / 256);
        float4* out4 = reinterpret_cast<float4*>(out);
        gather_rel_kernel<<<blocks, 256>>>(out4, 0, 0);
        gather_rel_kernel<<<blocks, 256>>>(out4, 1, 1);
        gather_rel_kernel<<<blocks, 256>>>(out4, 2, 3);
    }
}

// round 10
// speedup vs baseline: 1.2277x; 1.2277x over previous
#include <cuda_runtime.h>
#include <cuda_fp16.h>
#include <cstdint>

#define N_NODES 100000
#define N_EDGES 600000
#define IN_C    128
#define OUT_C   128
#define M_TILE  128
#define N_TILES ((N_NODES + M_TILE - 1) / M_TILE)   // 782
#define M_PAD   (N_TILES * M_TILE)                  // 100096
#define KCH     32
#define NCHUNK  (IN_C / KCH)                        // 4
#define A_STRIDE 132
#define BS_STRIDE 136
#define A_BUF   (M_TILE * A_STRIDE)
#define B_BUF   (KCH * BS_STRIDE)
#define SMEM_BYTES ((A_BUF + 2 * B_BUF) * 4)         // 102400

#define NB      (3 * N_NODES)
#define SCAN_BS 2048
#define SCAN_BLOCKS ((NB + SCAN_BS - 1) / SCAN_BS)   // 147

// h[r][M_PAD][128] in fp16 (halves gather read traffic)
__device__ __half2 g_hh[(size_t)3 * M_PAD * (OUT_C / 2)];
// CSR infrastructure
__device__ int g_cnt[NB];
__device__ int g_rowstart[NB + 1];
__device__ int g_cursor[NB];
__device__ int g_sorted[3 * N_EDGES];
__device__ int g_partial[SCAN_BLOCKS];

static __device__ __forceinline__ uint32_t tf32_rna(float x) {
    uint32_t y;
    asm("cvt.rna.tf32.f32 %0, %1;" : "=r"(y) : "f"(x));
    return y;
}

// ---------------------------------------------------------------------------
// 1) GEMM: h_j = x @ W_j (HMMA tf32). A tile staged once; fp16 epilogue.
// ---------------------------------------------------------------------------
__global__ __launch_bounds__(256, 2) void gemm_hmma_kernel(
        const float4* __restrict__ x4,
        const float* __restrict__ W0,
        const float* __restrict__ W1,
        const float* __restrict__ W2) {
    extern __shared__ float smem[];
    float* A  = smem;
    float* Bs[2] = { smem + A_BUF, smem + A_BUF + B_BUF };

    int tid  = threadIdx.x;
    int lane = tid & 31;
    int wid  = tid >> 5;
    int wr   = wid >> 2;
    int wc   = wid & 3;
    int g    = lane >> 2;
    int tg   = lane & 3;

    int tile_row0 = blockIdx.x * M_TILE;

    #pragma unroll
    for (int i = tid; i < 4096; i += 256) {
        int row = i >> 5, c4 = i & 31;
        int srow = tile_row0 + row;
        if (srow >= N_NODES) srow = 0;
        float4 v = __ldg(x4 + (size_t)srow * (IN_C / 4) + c4);
        uint32_t* p = reinterpret_cast<uint32_t*>(A + row * A_STRIDE + c4 * 4);
        p[0] = tf32_rna(v.x); p[1] = tf32_rna(v.y);
        p[2] = tf32_rna(v.z); p[3] = tf32_rna(v.w);
    }
    __syncthreads();

    const uint32_t* Au = reinterpret_cast<const uint32_t*>(A);

    for (int rel = 0; rel < 3; rel++) {
        const float* Wj = (rel == 0) ? W0 : (rel == 1 ? W1 : W2);
        __half2* hj = g_hh + (size_t)rel * M_PAD * (OUT_C / 2);

        auto stageB = [&](int c, int b) {
            float* B = Bs[b];
            #pragma unroll
            for (int i = tid; i < 1024; i += 256) {
                int k = i >> 5, n4 = i & 31;
                float4 v = __ldg(reinterpret_cast<const float4*>(
                                 Wj + (size_t)(c * KCH + k) * OUT_C) + n4);
                uint32_t* p = reinterpret_cast<uint32_t*>(B + k * BS_STRIDE + n4 * 4);
                p[0] = tf32_rna(v.x); p[1] = tf32_rna(v.y);
                p[2] = tf32_rna(v.z); p[3] = tf32_rna(v.w);
            }
        };

        float acc[4][4][4];
        #pragma unroll
        for (int mt = 0; mt < 4; mt++)
            #pragma unroll
            for (int nt = 0; nt < 4; nt++)
                #pragma unroll
                for (int r = 0; r < 4; r++) acc[mt][nt][r] = 0.f;

        stageB(0, 0);
        __syncthreads();

        for (int c = 0; c < NCHUNK; c++) {
            int b = c & 1;
            if (c + 1 < NCHUNK) stageB(c + 1, b ^ 1);

            const uint32_t* B = reinterpret_cast<const uint32_t*>(Bs[b]);

            #pragma unroll
            for (int ks = 0; ks < KCH / 8; ks++) {
                int kk = c * KCH + ks * 8;
                int kb = ks * 8;
                uint32_t af[4][4], bf[4][2];
                #pragma unroll
                for (int mt = 0; mt < 4; mt++) {
                    int m0 = wr * 64 + mt * 16 + g;
                    af[mt][0] = Au[(m0)     * A_STRIDE + kk + tg];
                    af[mt][1] = Au[(m0 + 8) * A_STRIDE + kk + tg];
                    af[mt][2] = Au[(m0)     * A_STRIDE + kk + tg + 4];
                    af[mt][3] = Au[(m0 + 8) * A_STRIDE + kk + tg + 4];
                }
                #pragma unroll
                for (int nt = 0; nt < 4; nt++) {
                    int n0 = wc * 32 + nt * 8 + g;
                    bf[nt][0] = B[(kb + tg)     * BS_STRIDE + n0];
                    bf[nt][1] = B[(kb + tg + 4) * BS_STRIDE + n0];
                }
                #pragma unroll
                for (int mt = 0; mt < 4; mt++)
                    #pragma unroll
                    for (int nt = 0; nt < 4; nt++) {
                        asm volatile(
                            "mma.sync.aligned.m16n8k8.row.col.f32.tf32.tf32.f32 "
                            "{%0,%1,%2,%3}, {%4,%5,%6,%7}, {%8,%9}, {%0,%1,%2,%3};"
                            : "+f"(acc[mt][nt][0]), "+f"(acc[mt][nt][1]),
                              "+f"(acc[mt][nt][2]), "+f"(acc[mt][nt][3])
                            : "r"(af[mt][0]), "r"(af[mt][1]),
                              "r"(af[mt][2]), "r"(af[mt][3]),
                              "r"(bf[nt][0]), "r"(bf[nt][1]));
                    }
            }
            __syncthreads();
        }

        // fp16 epilogue: each (c0,c1) pair -> one half2 store
        #pragma unroll
        for (int mt = 0; mt < 4; mt++) {
            int row = tile_row0 + wr * 64 + mt * 16 + g;
            #pragma unroll
            for (int nt = 0; nt < 4; nt++) {
                int col = wc * 32 + nt * 8 + 2 * tg;
                hj[(size_t)row * (OUT_C / 2) + col / 2] =
                    __floats2half2_rn(acc[mt][nt][0], acc[mt][nt][1]);
                hj[(size_t)(row + 8) * (OUT_C / 2) + col / 2] =
                    __floats2half2_rn(acc[mt][nt][2], acc[mt][nt][3]);
            }
        }
    }
}

// ---------------------------------------------------------------------------
// CSR build
// ---------------------------------------------------------------------------
__global__ void zero_cnt_kernel() {
    int i = blockIdx.x * blockDim.x + threadIdx.x;
    if (i < NB) g_cnt[i] = 0;
}

__global__ void count_kernel(const int* __restrict__ d0,
                             const int* __restrict__ d1,
                             const int* __restrict__ d2) {
    unsigned gid = blockIdx.x * blockDim.x + threadIdx.x;
    if (gid >= 3u * N_EDGES) return;
    int rel, e;
    const int* dp;
    if (gid < (unsigned)N_EDGES)          { rel = 0; e = gid;                dp = d0; }
    else if (gid < 2u * (unsigned)N_EDGES){ rel = 1; e = gid - N_EDGES;      dp = d1; }
    else                                  { rel = 2; e = gid - 2u * N_EDGES; dp = d2; }
    atomicAdd(&g_cnt[rel * N_NODES + __ldg(dp + e)], 1);
}

__global__ void scan_a_kernel() {
    __shared__ int sb[256];
    int t = threadIdx.x;
    int base = blockIdx.x * SCAN_BS + t * 8;
    int sum = 0;
    #pragma unroll
    for (int j = 0; j < 8; j++) {
        int idx = base + j;
        if (idx < NB) sum += g_cnt[idx];
    }
    sb[t] = sum;
    __syncthreads();
    for (int off = 128; off > 0; off >>= 1) {
        if (t < off) sb[t] += sb[t + off];
        __syncthreads();
    }
    if (t == 0) g_partial[blockIdx.x] = sb[0];
}

__global__ void scan_b_kernel() {
    __shared__ int sb[256];
    int t = threadIdx.x;
    int v = (t < SCAN_BLOCKS) ? g_partial[t] : 0;
    sb[t] = v;
    __syncthreads();
    for (int off = 1; off < 256; off <<= 1) {
        int add = (t >= off) ? sb[t - off] : 0;
        __syncthreads();
        sb[t] += add;
        __syncthreads();
    }
    if (t < SCAN_BLOCKS) g_partial[t] = sb[t] - v;
    if (t == 255) g_rowstart[NB] = sb[255];
}

__global__ void scan_c_kernel() {
    __shared__ int sb[256];
    int t = threadIdx.x;
    int base = blockIdx.x * SCAN_BS + t * 8;
    int v[8];
    int tsum = 0;
    #pragma unroll
    for (int j = 0; j < 8; j++) {
        int idx = base + j;
        v[j] = (idx < NB) ? g_cnt[idx] : 0;
        tsum += v[j];
    }
    sb[t] = tsum;
    __syncthreads();
    for (int off = 1; off < 256; off <<= 1) {
        int add = (t >= off) ? sb[t - off] : 0;
        __syncthreads();
        sb[t] += add;
        __syncthreads();
    }
    int run = g_partial[blockIdx.x] + sb[t] - tsum;
    #pragma unroll
    for (int j = 0; j < 8; j++) {
        int idx = base + j;
        if (idx < NB) {
            g_rowstart[idx] = run;
            g_cursor[idx] = run;
            run += v[j];
        }
    }
}

__global__ void fill_kernel(const int* __restrict__ s0, const int* __restrict__ d0,
                            const int* __restrict__ s1, const int* __restrict__ d1,
                            const int* __restrict__ s2, const int* __restrict__ d2) {
    unsigned gid = blockIdx.x * blockDim.x + threadIdx.x;
    if (gid >= 3u * N_EDGES) return;
    int rel, e;
    const int* sp;
    const int* dp;
    if (gid < (unsigned)N_EDGES)          { rel = 0; e = gid;                sp = s0; dp = d0; }
    else if (gid < 2u * (unsigned)N_EDGES){ rel = 1; e = gid - N_EDGES;      sp = s1; dp = d1; }
    else                                  { rel = 2; e = gid - 2u * N_EDGES; sp = s2; dp = d2; }
    int d = __ldg(dp + e);
    int pos = atomicAdd(&g_cursor[rel * N_NODES + d], 1);
    g_sorted[pos] = __ldg(sp + e);
}

// ---------------------------------------------------------------------------
// Gather (fused over 3 relations, fp16 h rows): one warp per node.
// Lane reads uint2 (4 halves = cols lane*4..+3), fp32 accumulate, relu, store.
// ---------------------------------------------------------------------------
__global__ void gather_kernel(float4* __restrict__ out4) {
    unsigned n    = (blockIdx.x * blockDim.x + threadIdx.x) >> 5;
    int      lane = threadIdx.x & 31;
    if (n >= (unsigned)N_NODES) return;

    const uint2* hrows = reinterpret_cast<const uint2*>(g_hh);
    float4 acc = make_float4(0.f, 0.f, 0.f, 0.f);

    #pragma unroll
    for (int rel = 0; rel < 3; rel++) {
        int idx = rel * N_NODES + (int)n;
        int e   = __ldg(&g_rowstart[idx]);
        int end = __ldg(&g_rowstart[idx + 1]);
        size_t hbase = (size_t)rel * M_PAD * (OUT_C / 8);   // uint2 units per row = 16

        for (; e + 3 < end; e += 4) {
            int s0 = __ldg(&g_sorted[e]);
            int s1 = __ldg(&g_sorted[e + 1]);
            int s2 = __ldg(&g_sorted[e + 2]);
            int s3 = __ldg(&g_sorted[e + 3]);
            uint2 u0 = __ldg(hrows + hbase + (size_t)s0 * (OUT_C / 8) + (lane >> 1) * 2 + (lane & 1));
            // NOTE: simpler exact mapping below; keep uniform:
            u0 = __ldg(hrows + hbase + (size_t)s0 * (OUT_C / 8) + lane % 16 + (lane / 16) * 0);
            (void)u0;
            // fall through to scalar path (should not happen) -- replaced below
            break;
        }
        // clean scalar-mapped loop: each lane owns uint2 index `lane` within
        // the 16-uint2... lane 0..31 but row has 16 uint2. Use half-warp pairs:
        // lanes 0..15 cover the row; lanes 16..31 duplicate columns of lanes 0..15.
        // To keep every lane productive and the store mapping simple, re-derive:
        // lane owns halves [lane*4, lane*4+4) = uint2 index lane/2... conflict.
        // -> use explicit 8-byte offset per lane: byte off = lane*8 within 256B row.
        e = __ldg(&g_rowstart[idx]);
        const char* hb = reinterpret_cast<const char*>(g_hh)
                       + (size_t)rel * M_PAD * OUT_C * 2;

        for (; e + 3 < end; e += 4) {
            int s0 = __ldg(&g_sorted[e]);
            int s1 = __ldg(&g_sorted[e + 1]);
            int s2 = __ldg(&g_sorted[e + 2]);
            int s3 = __ldg(&g_sorted[e + 3]);
            uint2 u0 = __ldg(reinterpret_cast<const uint2*>(hb + (size_t)s0 * 256 + lane * 8));
            uint2 u1 = __ldg(reinterpret_cast<const uint2*>(hb + (size_t)s1 * 256 + lane * 8));
            uint2 u2 = __ldg(reinterpret_cast<const uint2*>(hb + (size_t)s2 * 256 + lane * 8));
            uint2 u3 = __ldg(reinterpret_cast<const uint2*>(hb + (size_t)s3 * 256 + lane * 8));
            #pragma unroll
            for (int j = 0; j < 4; j++) {
                uint2 u = (j == 0) ? u0 : (j == 1) ? u1 : (j == 2) ? u2 : u3;
                float2 f0 = __half22float2(*reinterpret_cast<__half2*>(&u.x));
                float2 f1 = __half22float2(*reinterpret_cast<__half2*>(&u.y));
                acc.x += f0.x; acc.y += f0.y; acc.z += f1.x; acc.w += f1.y;
            }
        }
        for (; e < end; e++) {
            int s0 = __ldg(&g_sorted[e]);
            uint2 u = __ldg(reinterpret_cast<const uint2*>(hb + (size_t)s0 * 256 + lane * 8));
            float2 f0 = __half22float2(*reinterpret_cast<__half2*>(&u.x));
            float2 f1 = __half22float2(*reinterpret_cast<__half2*>(&u.y));
            acc.x += f0.x; acc.y += f0.y; acc.z += f1.x; acc.w += f1.y;
        }
    }

    acc.x = fmaxf(acc.x, 0.f); acc.y = fmaxf(acc.y, 0.f);
    acc.z = fmaxf(acc.z, 0.f); acc.w = fmaxf(acc.w, 0.f);
    out4[(size_t)n * (OUT_C / 4) + lane] = acc;
}

// ---------------------------------------------------------------------------
// launch
// ---------------------------------------------------------------------------
extern "C" void kernel_launch(void* const* d_in, const int* in_sizes, int n_in,
                              void* d_out, int out_size) {
    const float* x  = (const float*)d_in[0];
    const float* W0 = (const float*)d_in[1];
    const float* W1 = (const float*)d_in[2];
    const float* W2 = (const float*)d_in[3];
    const int* s0 = (const int*)d_in[4];
    const int* d0 = (const int*)d_in[5];
    const int* s1 = (const int*)d_in[6];
    const int* d1 = (const int*)d_in[7];
    const int* s2 = (const int*)d_in[8];
    const int* d2 = (const int*)d_in[9];
    float* out = (float*)d_out;

    // CSR build
    zero_cnt_kernel<<<(NB + 255) / 256, 256>>>();
    count_kernel<<<(3 * N_EDGES + 255) / 256, 256>>>(d0, d1, d2);
    scan_a_kernel<<<SCAN_BLOCKS, 256>>>();
    scan_b_kernel<<<1, 256>>>();
    scan_c_kernel<<<SCAN_BLOCKS, 256>>>();
    fill_kernel<<<(3 * N_EDGES + 255) / 256, 256>>>(s0, d0, s1, d1, s2, d2);

    // GEMM: h_r = x @ W_r (fp16 output)
    {
        static bool attr_set = false;   // idempotent attribute set
        if (!attr_set) {
            cudaFuncSetAttribute(gemm_hmma_kernel,
                                 cudaFuncAttributeMaxDynamicSharedMemorySize,
                                 SMEM_BYTES);
            attr_set = true;
        }
        gemm_hmma_kernel<<<N_TILES, 256, SMEM_BYTES>>>(
            reinterpret_cast<const float4*>(x), W0, W1, W2);
    }

    // Gather + relu (fused, one warp per node)
    {
        long long threads = (long long)N_NODES * 32;
        int blocks = (int)((threads + 255) / 256);
        gather_kernel<<<blocks, 256>>>(reinterpret_cast<float4*>(out));
    }
}

// round 11
// speedup vs baseline: 1.2316x; 1.0032x over previous
#include <cuda_runtime.h>
#include <cuda_fp16.h>
#include <cstdint>

#define N_NODES 100000
#define N_EDGES 600000
#define IN_C    128
#define OUT_C   128
#define M_TILE  128
#define N_TILES ((N_NODES + M_TILE - 1) / M_TILE)   // 782
#define M_PAD   (N_TILES * M_TILE)                  // 100096
#define KCH     32
#define NCHUNK  (IN_C / KCH)                        // 4
#define A_STRIDE 132
#define BS_STRIDE 136
#define A_BUF   (M_TILE * A_STRIDE)
#define B_BUF   (KCH * BS_STRIDE)
#define SMEM_BYTES ((A_BUF + 2 * B_BUF) * 4)         // 102400

#define NB      (3 * N_NODES)
#define SCAN_BS 2048
#define SCAN_BLOCKS ((NB + SCAN_BS - 1) / SCAN_BS)   // 147

// h[r][M_PAD][128] in fp16
__device__ __half2 g_hh[(size_t)3 * M_PAD * (OUT_C / 2)];
// CSR infrastructure. g_cnt starts zeroed (module load) and is re-zeroed by
// scan_c at the end of every executed run -> deterministic across replays.
__device__ int g_cnt[NB];
__device__ int g_rowstart[NB + 1];
__device__ int g_cursor[NB];
__device__ int g_sorted[3 * N_EDGES];
__device__ int g_partial[SCAN_BLOCKS];

static __device__ __forceinline__ uint32_t tf32_rna(float x) {
    uint32_t y;
    asm("cvt.rna.tf32.f32 %0, %1;" : "=r"(y) : "f"(x));
    return y;
}

// ---------------------------------------------------------------------------
// 1) GEMM: h_j = x @ W_j (HMMA tf32). A tile staged once; fp16 epilogue.
//    (unchanged from R10)
// ---------------------------------------------------------------------------
__global__ __launch_bounds__(256, 2) void gemm_hmma_kernel(
        const float4* __restrict__ x4,
        const float* __restrict__ W0,
        const float* __restrict__ W1,
        const float* __restrict__ W2) {
    extern __shared__ float smem[];
    float* A  = smem;
    float* Bs[2] = { smem + A_BUF, smem + A_BUF + B_BUF };

    int tid  = threadIdx.x;
    int lane = tid & 31;
    int wid  = tid >> 5;
    int wr   = wid >> 2;
    int wc   = wid & 3;
    int g    = lane >> 2;
    int tg   = lane & 3;

    int tile_row0 = blockIdx.x * M_TILE;

    #pragma unroll
    for (int i = tid; i < 4096; i += 256) {
        int row = i >> 5, c4 = i & 31;
        int srow = tile_row0 + row;
        if (srow >= N_NODES) srow = 0;
        float4 v = __ldg(x4 + (size_t)srow * (IN_C / 4) + c4);
        uint32_t* p = reinterpret_cast<uint32_t*>(A + row * A_STRIDE + c4 * 4);
        p[0] = tf32_rna(v.x); p[1] = tf32_rna(v.y);
        p[2] = tf32_rna(v.z); p[3] = tf32_rna(v.w);
    }
    __syncthreads();

    const uint32_t* Au = reinterpret_cast<const uint32_t*>(A);

    for (int rel = 0; rel < 3; rel++) {
        const float* Wj = (rel == 0) ? W0 : (rel == 1 ? W1 : W2);
        __half2* hj = g_hh + (size_t)rel * M_PAD * (OUT_C / 2);

        auto stageB = [&](int c, int b) {
            float* B = Bs[b];
            #pragma unroll
            for (int i = tid; i < 1024; i += 256) {
                int k = i >> 5, n4 = i & 31;
                float4 v = __ldg(reinterpret_cast<const float4*>(
                                 Wj + (size_t)(c * KCH + k) * OUT_C) + n4);
                uint32_t* p = reinterpret_cast<uint32_t*>(B + k * BS_STRIDE + n4 * 4);
                p[0] = tf32_rna(v.x); p[1] = tf32_rna(v.y);
                p[2] = tf32_rna(v.z); p[3] = tf32_rna(v.w);
            }
        };

        float acc[4][4][4];
        #pragma unroll
        for (int mt = 0; mt < 4; mt++)
            #pragma unroll
            for (int nt = 0; nt < 4; nt++)
                #pragma unroll
                for (int r = 0; r < 4; r++) acc[mt][nt][r] = 0.f;

        stageB(0, 0);
        __syncthreads();

        for (int c = 0; c < NCHUNK; c++) {
            int b = c & 1;
            if (c + 1 < NCHUNK) stageB(c + 1, b ^ 1);

            const uint32_t* B = reinterpret_cast<const uint32_t*>(Bs[b]);

            #pragma unroll
            for (int ks = 0; ks < KCH / 8; ks++) {
                int kk = c * KCH + ks * 8;
                int kb = ks * 8;
                uint32_t af[4][4], bf[4][2];
                #pragma unroll
                for (int mt = 0; mt < 4; mt++) {
                    int m0 = wr * 64 + mt * 16 + g;
                    af[mt][0] = Au[(m0)     * A_STRIDE + kk + tg];
                    af[mt][1] = Au[(m0 + 8) * A_STRIDE + kk + tg];
                    af[mt][2] = Au[(m0)     * A_STRIDE + kk + tg + 4];
                    af[mt][3] = Au[(m0 + 8) * A_STRIDE + kk + tg + 4];
                }
                #pragma unroll
                for (int nt = 0; nt < 4; nt++) {
                    int n0 = wc * 32 + nt * 8 + g;
                    bf[nt][0] = B[(kb + tg)     * BS_STRIDE + n0];
                    bf[nt][1] = B[(kb + tg + 4) * BS_STRIDE + n0];
                }
                #pragma unroll
                for (int mt = 0; mt < 4; mt++)
                    #pragma unroll
                    for (int nt = 0; nt < 4; nt++) {
                        asm volatile(
                            "mma.sync.aligned.m16n8k8.row.col.f32.tf32.tf32.f32 "
                            "{%0,%1,%2,%3}, {%4,%5,%6,%7}, {%8,%9}, {%0,%1,%2,%3};"
                            : "+f"(acc[mt][nt][0]), "+f"(acc[mt][nt][1]),
                              "+f"(acc[mt][nt][2]), "+f"(acc[mt][nt][3])
                            : "r"(af[mt][0]), "r"(af[mt][1]),
                              "r"(af[mt][2]), "r"(af[mt][3]),
                              "r"(bf[nt][0]), "r"(bf[nt][1]));
                    }
            }
            __syncthreads();
        }

        #pragma unroll
        for (int mt = 0; mt < 4; mt++) {
            int row = tile_row0 + wr * 64 + mt * 16 + g;
            #pragma unroll
            for (int nt = 0; nt < 4; nt++) {
                int col = wc * 32 + nt * 8 + 2 * tg;
                hj[(size_t)row * (OUT_C / 2) + col / 2] =
                    __floats2half2_rn(acc[mt][nt][0], acc[mt][nt][1]);
                hj[(size_t)(row + 8) * (OUT_C / 2) + col / 2] =
                    __floats2half2_rn(acc[mt][nt][2], acc[mt][nt][3]);
            }
        }
    }
}

// ---------------------------------------------------------------------------
// CSR build: count -> scan_a -> scan_c (self-base + cnt re-zero) -> fill
// ---------------------------------------------------------------------------
__global__ void count_kernel(const int* __restrict__ d0,
                             const int* __restrict__ d1,
                             const int* __restrict__ d2) {
    unsigned gid = blockIdx.x * blockDim.x + threadIdx.x;
    if (gid >= 3u * N_EDGES) return;
    int rel, e;
    const int* dp;
    if (gid < (unsigned)N_EDGES)          { rel = 0; e = gid;                dp = d0; }
    else if (gid < 2u * (unsigned)N_EDGES){ rel = 1; e = gid - N_EDGES;      dp = d1; }
    else                                  { rel = 2; e = gid - 2u * N_EDGES; dp = d2; }
    atomicAdd(&g_cnt[rel * N_NODES + __ldg(dp + e)], 1);
}

__global__ void scan_a_kernel() {      // per-block totals
    __shared__ int sb[256];
    int t = threadIdx.x;
    int base = blockIdx.x * SCAN_BS + t * 8;
    int sum = 0;
    #pragma unroll
    for (int j = 0; j < 8; j++) {
        int idx = base + j;
        if (idx < NB) sum += g_cnt[idx];
    }
    sb[t] = sum;
    __syncthreads();
    for (int off = 128; off > 0; off >>= 1) {
        if (t < off) sb[t] += sb[t + off];
        __syncthreads();
    }
    if (t == 0) g_partial[blockIdx.x] = sb[0];
}

__global__ void scan_c_kernel() {
    __shared__ int sb[256];
    __shared__ int base_sh;
    int t = threadIdx.x;

    // block base = sum of partials of preceding blocks (SCAN_BLOCKS <= 256)
    int p = (t < (int)blockIdx.x) ? g_partial[t] : 0;
    sb[t] = p;
    __syncthreads();
    for (int off = 128; off > 0; off >>= 1) {
        if (t < off) sb[t] += sb[t + off];
        __syncthreads();
    }
    if (t == 0) base_sh = sb[0];
    __syncthreads();

    int base = blockIdx.x * SCAN_BS + t * 8;
    int v[8];
    int tsum = 0;
    #pragma unroll
    for (int j = 0; j < 8; j++) {
        int idx = base + j;
        v[j] = (idx < NB) ? g_cnt[idx] : 0;
        if (idx < NB) g_cnt[idx] = 0;          // re-zero for the next run
        tsum += v[j];
    }
    sb[t] = tsum;
    __syncthreads();
    for (int off = 1; off < 256; off <<= 1) {
        int add = (t >= off) ? sb[t - off] : 0;
        __syncthreads();
        sb[t] += add;
        __syncthreads();
    }
    int run = base_sh + sb[t] - tsum;          // exclusive prefix
    #pragma unroll
    for (int j = 0; j < 8; j++) {
        int idx = base + j;
        if (idx < NB) {
            g_rowstart[idx] = run;
            g_cursor[idx] = run;
            run += v[j];
        }
    }
    if (blockIdx.x == 0 && t == 0) g_rowstart[NB] = 3 * N_EDGES;
}

__global__ void fill_kernel(const int* __restrict__ s0, const int* __restrict__ d0,
                            const int* __restrict__ s1, const int* __restrict__ d1,
                            const int* __restrict__ s2, const int* __restrict__ d2) {
    unsigned gid = blockIdx.x * blockDim.x + threadIdx.x;
    if (gid >= 3u * N_EDGES) return;
    int rel, e;
    const int* sp;
    const int* dp;
    if (gid < (unsigned)N_EDGES)          { rel = 0; e = gid;                sp = s0; dp = d0; }
    else if (gid < 2u * (unsigned)N_EDGES){ rel = 1; e = gid - N_EDGES;      sp = s1; dp = d1; }
    else                                  { rel = 2; e = gid - 2u * N_EDGES; sp = s2; dp = d2; }
    int d = __ldg(dp + e);
    int pos = atomicAdd(&g_cursor[rel * N_NODES + d], 1);
    g_sorted[pos] = __ldg(sp + e);
}

// ---------------------------------------------------------------------------
// Gather (fused 3 relations, fp16 h rows): one warp per node; lane owns 8B
// of the 256B row. Rowstart pairs for all relations loaded upfront.
// ---------------------------------------------------------------------------
static __device__ __forceinline__ void accum_segment(
        float4& acc, int e, int end, const char* hb, int lane) {
    for (; e + 3 < end; e += 4) {
        int s0 = __ldg(&g_sorted[e]);
        int s1 = __ldg(&g_sorted[e + 1]);
        int s2 = __ldg(&g_sorted[e + 2]);
        int s3 = __ldg(&g_sorted[e + 3]);
        uint2 u0 = __ldg(reinterpret_cast<const uint2*>(hb + (size_t)s0 * 256 + lane * 8));
        uint2 u1 = __ldg(reinterpret_cast<const uint2*>(hb + (size_t)s1 * 256 + lane * 8));
        uint2 u2 = __ldg(reinterpret_cast<const uint2*>(hb + (size_t)s2 * 256 + lane * 8));
        uint2 u3 = __ldg(reinterpret_cast<const uint2*>(hb + (size_t)s3 * 256 + lane * 8));
        #pragma unroll
        for (int j = 0; j < 4; j++) {
            uint2 u = (j == 0) ? u0 : (j == 1) ? u1 : (j == 2) ? u2 : u3;
            float2 f0 = __half22float2(*reinterpret_cast<__half2*>(&u.x));
            float2 f1 = __half22float2(*reinterpret_cast<__half2*>(&u.y));
            acc.x += f0.x; acc.y += f0.y; acc.z += f1.x; acc.w += f1.y;
        }
    }
    for (; e < end; e++) {
        int s0 = __ldg(&g_sorted[e]);
        uint2 u = __ldg(reinterpret_cast<const uint2*>(hb + (size_t)s0 * 256 + lane * 8));
        float2 f0 = __half22float2(*reinterpret_cast<__half2*>(&u.x));
        float2 f1 = __half22float2(*reinterpret_cast<__half2*>(&u.y));
        acc.x += f0.x; acc.y += f0.y; acc.z += f1.x; acc.w += f1.y;
    }
}

__global__ void gather_kernel(float4* __restrict__ out4) {
    unsigned n    = (blockIdx.x * blockDim.x + threadIdx.x) >> 5;
    int      lane = threadIdx.x & 31;
    if (n >= (unsigned)N_NODES) return;

    // all segment bounds upfront (6 independent loads)
    int e0 = __ldg(&g_rowstart[n]);
    int f0 = __ldg(&g_rowstart[n + 1]);
    int e1 = __ldg(&g_rowstart[N_NODES + n]);
    int f1 = __ldg(&g_rowstart[N_NODES + n + 1]);
    int e2 = __ldg(&g_rowstart[2 * N_NODES + n]);
    int f2 = __ldg(&g_rowstart[2 * N_NODES + n + 1]);

    const char* hb = reinterpret_cast<const char*>(g_hh);
    const size_t relstride = (size_t)M_PAD * OUT_C * 2;

    float4 acc = make_float4(0.f, 0.f, 0.f, 0.f);
    accum_segment(acc, e0, f0, hb,                 lane);
    accum_segment(acc, e1, f1, hb + relstride,     lane);
    accum_segment(acc, e2, f2, hb + 2 * relstride, lane);

    acc.x = fmaxf(acc.x, 0.f); acc.y = fmaxf(acc.y, 0.f);
    acc.z = fmaxf(acc.z, 0.f); acc.w = fmaxf(acc.w, 0.f);
    out4[(size_t)n * (OUT_C / 4) + lane] = acc;
}

// ---------------------------------------------------------------------------
// launch
// ---------------------------------------------------------------------------
extern "C" void kernel_launch(void* const* d_in, const int* in_sizes, int n_in,
                              void* d_out, int out_size) {
    const float* x  = (const float*)d_in[0];
    const float* W0 = (const float*)d_in[1];
    const float* W1 = (const float*)d_in[2];
    const float* W2 = (const float*)d_in[3];
    const int* s0 = (const int*)d_in[4];
    const int* d0 = (const int*)d_in[5];
    const int* s1 = (const int*)d_in[6];
    const int* d1 = (const int*)d_in[7];
    const int* s2 = (const int*)d_in[8];
    const int* d2 = (const int*)d_in[9];
    float* out = (float*)d_out;

    // CSR build (g_cnt arrives zeroed; scan_c re-zeroes it for the next run)
    count_kernel<<<(3 * N_EDGES + 255) / 256, 256>>>(d0, d1, d2);
    scan_a_kernel<<<SCAN_BLOCKS, 256>>>();
    scan_c_kernel<<<SCAN_BLOCKS, 256>>>();
    fill_kernel<<<(3 * N_EDGES + 255) / 256, 256>>>(s0, d0, s1, d1, s2, d2);

    // GEMM: h_r = x @ W_r (fp16 output)
    {
        static bool attr_set = false;   // idempotent attribute set
        if (!attr_set) {
            cudaFuncSetAttribute(gemm_hmma_kernel,
                                 cudaFuncAttributeMaxDynamicSharedMemorySize,
                                 SMEM_BYTES);
            attr_set = true;
        }
        gemm_hmma_kernel<<<N_TILES, 256, SMEM_BYTES>>>(
            reinterpret_cast<const float4*>(x), W0, W1, W2);
    }

    // Gather + relu (fused, one warp per node)
    {
        long long threads = (long long)N_NODES * 32;
        int blocks = (int)((threads + 255) / 256);
        gather_kernel<<<blocks, 256>>>(reinterpret_cast<float4*>(out));
    }
}

// round 12
// speedup vs baseline: 1.5937x; 1.2940x over previous
#include <cuda_runtime.h>
#include <cuda_fp16.h>
#include <cstdint>

#define N_NODES 100000
#define N_EDGES 600000
#define IN_C    128
#define OUT_C   128
#define M_TILE  128
#define N_TILES ((N_NODES + M_TILE - 1) / M_TILE)   // 782
#define M_PAD   (N_TILES * M_TILE)                  // 100096

#define AH_STRIDE 136                                // halves per A row (272 B)
#define BH_STRIDE 136                                // halves per B k-row
#define A_BYTES   (M_TILE * AH_STRIDE * 2)           // 34816
#define B_BYTES   (IN_C  * BH_STRIDE * 2)            // 34816
#define SMEM_BYTES (A_BYTES + B_BYTES)               // 69632

#define NB      (3 * N_NODES)
#define SCAN_BS 2048
#define SCAN_BLOCKS ((NB + SCAN_BS - 1) / SCAN_BS)   // 147

// h[r][M_PAD][128] in fp16
__device__ __half2 g_hh[(size_t)3 * M_PAD * (OUT_C / 2)];
// CSR infrastructure. g_cnt starts zeroed (module load) and is re-zeroed by
// scan_c each executed run -> deterministic across replays.
__device__ int g_cnt[NB];
__device__ int g_rowstart[NB + 1];
__device__ int g_cursor[NB];
__device__ int g_sorted[3 * N_EDGES];
__device__ int g_partial[SCAN_BLOCKS];

// ---------------------------------------------------------------------------
// 1) GEMM: h_j = x @ W_j via mma.sync.m16n8k16.f16 + ldmatrix.
//    A (fp16, [row][k]) staged once; B (fp16, [k][n]) staged per relation.
// ---------------------------------------------------------------------------
__global__ __launch_bounds__(256, 2) void gemm_hmma_kernel(
        const float4* __restrict__ x4,
        const float* __restrict__ W0,
        const float* __restrict__ W1,
        const float* __restrict__ W2) {
    extern __shared__ char smem[];
    char* As = smem;                 // 128 x 136 halves
    char* Bs = smem + A_BYTES;       // 128 x 136 halves

    int tid  = threadIdx.x;
    int lane = tid & 31;
    int wid  = tid >> 5;
    int wr   = wid >> 2;             // 0..1  (64-row slab)
    int wc   = wid & 3;              // 0..3  (32-col slab)
    int g    = lane >> 2;
    int tg   = lane & 3;

    int tile_row0 = blockIdx.x * M_TILE;

    uint32_t As_u = (uint32_t)__cvta_generic_to_shared(As);
    uint32_t Bs_u = (uint32_t)__cvta_generic_to_shared(Bs);

    // stage A once: fp32 -> fp16, [row][k], coalesced 8B stores
    #pragma unroll
    for (int i = tid; i < 4096; i += 256) {
        int row = i >> 5, c4 = i & 31;
        int srow = tile_row0 + row;
        if (srow >= N_NODES) srow = 0;               // pad rows: any value
        float4 v = __ldg(x4 + (size_t)srow * (IN_C / 4) + c4);
        __half2 h0 = __floats2half2_rn(v.x, v.y);
        __half2 h1 = __floats2half2_rn(v.z, v.w);
        uint2 u = { *reinterpret_cast<uint32_t*>(&h0),
                    *reinterpret_cast<uint32_t*>(&h1) };
        *reinterpret_cast<uint2*>(As + row * (AH_STRIDE * 2) + c4 * 8) = u;
    }

    for (int rel = 0; rel < 3; rel++) {
        const float* Wj = (rel == 0) ? W0 : (rel == 1 ? W1 : W2);
        __half2* hj = g_hh + (size_t)rel * M_PAD * (OUT_C / 2);

        __syncthreads();             // prior mainloop done reading Bs (and A staged)
        #pragma unroll
        for (int i = tid; i < 4096; i += 256) {      // B: [k][n] fp16, coalesced
            int k = i >> 5, n4 = i & 31;
            float4 v = __ldg(reinterpret_cast<const float4*>(
                             Wj + (size_t)k * OUT_C) + n4);
            __half2 h0 = __floats2half2_rn(v.x, v.y);
            __half2 h1 = __floats2half2_rn(v.z, v.w);
            uint2 u = { *reinterpret_cast<uint32_t*>(&h0),
                        *reinterpret_cast<uint32_t*>(&h1) };
            *reinterpret_cast<uint2*>(Bs + k * (BH_STRIDE * 2) + n4 * 8) = u;
        }
        __syncthreads();

        float acc[4][4][4];
        #pragma unroll
        for (int mt = 0; mt < 4; mt++)
            #pragma unroll
            for (int nt = 0; nt < 4; nt++)
                #pragma unroll
                for (int r = 0; r < 4; r++) acc[mt][nt][r] = 0.f;

        #pragma unroll
        for (int ks = 0; ks < IN_C / 16; ks++) {     // 8 k-steps of 16
            uint32_t a[4][4], b[4][2];
            #pragma unroll
            for (int mt = 0; mt < 4; mt++) {
                int arow = wr * 64 + mt * 16 + (lane & 15);
                uint32_t addr = As_u + arow * (AH_STRIDE * 2)
                              + ks * 32 + ((lane >> 4) * 16);
                asm volatile(
                    "ldmatrix.sync.aligned.m8n8.x4.shared.b16 {%0,%1,%2,%3}, [%4];"
                    : "=r"(a[mt][0]), "=r"(a[mt][1]),
                      "=r"(a[mt][2]), "=r"(a[mt][3])
                    : "r"(addr));
            }
            #pragma unroll
            for (int nt = 0; nt < 4; nt++) {
                int brow = ks * 16 + (lane & 15);
                uint32_t addr = Bs_u + brow * (BH_STRIDE * 2)
                              + (wc * 32 + nt * 8) * 2;
                asm volatile(
                    "ldmatrix.sync.aligned.m8n8.x2.trans.shared.b16 {%0,%1}, [%2];"
                    : "=r"(b[nt][0]), "=r"(b[nt][1])
                    : "r"(addr));
            }
            #pragma unroll
            for (int mt = 0; mt < 4; mt++)
                #pragma unroll
                for (int nt = 0; nt < 4; nt++) {
                    asm volatile(
                        "mma.sync.aligned.m16n8k16.row.col.f32.f16.f16.f32 "
                        "{%0,%1,%2,%3}, {%4,%5,%6,%7}, {%8,%9}, {%0,%1,%2,%3};"
                        : "+f"(acc[mt][nt][0]), "+f"(acc[mt][nt][1]),
                          "+f"(acc[mt][nt][2]), "+f"(acc[mt][nt][3])
                        : "r"(a[mt][0]), "r"(a[mt][1]),
                          "r"(a[mt][2]), "r"(a[mt][3]),
                          "r"(b[nt][0]), "r"(b[nt][1]));
                }
        }

        // epilogue: acc{0,1}=(row g), acc{2,3}=(row g+8); fp16 half2 stores
        #pragma unroll
        for (int mt = 0; mt < 4; mt++) {
            int row = tile_row0 + wr * 64 + mt * 16 + g;
            #pragma unroll
            for (int nt = 0; nt < 4; nt++) {
                int col = wc * 32 + nt * 8 + 2 * tg;
                hj[(size_t)row * (OUT_C / 2) + col / 2] =
                    __floats2half2_rn(acc[mt][nt][0], acc[mt][nt][1]);
                hj[(size_t)(row + 8) * (OUT_C / 2) + col / 2] =
                    __floats2half2_rn(acc[mt][nt][2], acc[mt][nt][3]);
            }
        }
    }
}

// ---------------------------------------------------------------------------
// CSR build: count (x4 int4) -> scan_a -> scan_c -> fill (x4 int4)
// ---------------------------------------------------------------------------
#define E4 (N_EDGES / 4)   // 150000

__global__ void count_kernel(const int* __restrict__ d0,
                             const int* __restrict__ d1,
                             const int* __restrict__ d2) {
    unsigned gid = blockIdx.x * blockDim.x + threadIdx.x;
    if (gid >= 3u * E4) return;
    int rel = gid / E4;
    int e4  = gid % E4;
    const int* dp = (rel == 0) ? d0 : (rel == 1 ? d1 : d2);
    int4 d = __ldg(reinterpret_cast<const int4*>(dp) + e4);
    int* base = g_cnt + rel * N_NODES;
    atomicAdd(base + d.x, 1);
    atomicAdd(base + d.y, 1);
    atomicAdd(base + d.z, 1);
    atomicAdd(base + d.w, 1);
}

__global__ void scan_a_kernel() {
    __shared__ int sb[256];
    int t = threadIdx.x;
    int base = blockIdx.x * SCAN_BS + t * 8;
    int sum = 0;
    #pragma unroll
    for (int j = 0; j < 8; j++) {
        int idx = base + j;
        if (idx < NB) sum += g_cnt[idx];
    }
    sb[t] = sum;
    __syncthreads();
    for (int off = 128; off > 0; off >>= 1) {
        if (t < off) sb[t] += sb[t + off];
        __syncthreads();
    }
    if (t == 0) g_partial[blockIdx.x] = sb[0];
}

__global__ void scan_c_kernel() {
    __shared__ int sb[256];
    __shared__ int base_sh;
    int t = threadIdx.x;

    int p = (t < (int)blockIdx.x) ? g_partial[t] : 0;
    sb[t] = p;
    __syncthreads();
    for (int off = 128; off > 0; off >>= 1) {
        if (t < off) sb[t] += sb[t + off];
        __syncthreads();
    }
    if (t == 0) base_sh = sb[0];
    __syncthreads();

    int base = blockIdx.x * SCAN_BS + t * 8;
    int v[8];
    int tsum = 0;
    #pragma unroll
    for (int j = 0; j < 8; j++) {
        int idx = base + j;
        v[j] = (idx < NB) ? g_cnt[idx] : 0;
        if (idx < NB) g_cnt[idx] = 0;          // re-zero for next run
        tsum += v[j];
    }
    sb[t] = tsum;
    __syncthreads();
    for (int off = 1; off < 256; off <<= 1) {
        int add = (t >= off) ? sb[t - off] : 0;
        __syncthreads();
        sb[t] += add;
        __syncthreads();
    }
    int run = base_sh + sb[t] - tsum;
    #pragma unroll
    for (int j = 0; j < 8; j++) {
        int idx = base + j;
        if (idx < NB) {
            g_rowstart[idx] = run;
            g_cursor[idx] = run;
            run += v[j];
        }
    }
    if (blockIdx.x == 0 && t == 0) g_rowstart[NB] = 3 * N_EDGES;
}

__global__ void fill_kernel(const int* __restrict__ s0, const int* __restrict__ d0,
                            const int* __restrict__ s1, const int* __restrict__ d1,
                            const int* __restrict__ s2, const int* __restrict__ d2) {
    unsigned gid = blockIdx.x * blockDim.x + threadIdx.x;
    if (gid >= 3u * E4) return;
    int rel = gid / E4;
    int e4  = gid % E4;
    const int* sp = (rel == 0) ? s0 : (rel == 1 ? s1 : s2);
    const int* dp = (rel == 0) ? d0 : (rel == 1 ? d1 : d2);
    int4 s = __ldg(reinterpret_cast<const int4*>(sp) + e4);
    int4 d = __ldg(reinterpret_cast<const int4*>(dp) + e4);
    int* cur = g_cursor + rel * N_NODES;
    g_sorted[atomicAdd(cur + d.x, 1)] = s.x;
    g_sorted[atomicAdd(cur + d.y, 1)] = s.y;
    g_sorted[atomicAdd(cur + d.z, 1)] = s.z;
    g_sorted[atomicAdd(cur + d.w, 1)] = s.w;
}

// ---------------------------------------------------------------------------
// Gather (fused 3 relations, fp16 h rows): one warp per node (unchanged R11)
// ---------------------------------------------------------------------------
static __device__ __forceinline__ void accum_segment(
        float4& acc, int e, int end, const char* hb, int lane) {
    for (; e + 3 < end; e += 4) {
        int s0 = __ldg(&g_sorted[e]);
        int s1 = __ldg(&g_sorted[e + 1]);
        int s2 = __ldg(&g_sorted[e + 2]);
        int s3 = __ldg(&g_sorted[e + 3]);
        uint2 u0 = __ldg(reinterpret_cast<const uint2*>(hb + (size_t)s0 * 256 + lane * 8));
        uint2 u1 = __ldg(reinterpret_cast<const uint2*>(hb + (size_t)s1 * 256 + lane * 8));
        uint2 u2 = __ldg(reinterpret_cast<const uint2*>(hb + (size_t)s2 * 256 + lane * 8));
        uint2 u3 = __ldg(reinterpret_cast<const uint2*>(hb + (size_t)s3 * 256 + lane * 8));
        #pragma unroll
        for (int j = 0; j < 4; j++) {
            uint2 u = (j == 0) ? u0 : (j == 1) ? u1 : (j == 2) ? u2 : u3;
            float2 f0 = __half22float2(*reinterpret_cast<__half2*>(&u.x));
            float2 f1 = __half22float2(*reinterpret_cast<__half2*>(&u.y));
            acc.x += f0.x; acc.y += f0.y; acc.z += f1.x; acc.w += f1.y;
        }
    }
    for (; e < end; e++) {
        int s0 = __ldg(&g_sorted[e]);
        uint2 u = __ldg(reinterpret_cast<const uint2*>(hb + (size_t)s0 * 256 + lane * 8));
        float2 f0 = __half22float2(*reinterpret_cast<__half2*>(&u.x));
        float2 f1 = __half22float2(*reinterpret_cast<__half2*>(&u.y));
        acc.x += f0.x; acc.y += f0.y; acc.z += f1.x; acc.w += f1.y;
    }
}

__global__ void gather_kernel(float4* __restrict__ out4) {
    unsigned n    = (blockIdx.x * blockDim.x + threadIdx.x) >> 5;
    int      lane = threadIdx.x & 31;
    if (n >= (unsigned)N_NODES) return;

    int e0 = __ldg(&g_rowstart[n]);
    int f0 = __ldg(&g_rowstart[n + 1]);
    int e1 = __ldg(&g_rowstart[N_NODES + n]);
    int f1 = __ldg(&g_rowstart[N_NODES + n + 1]);
    int e2 = __ldg(&g_rowstart[2 * N_NODES + n]);
    int f2 = __ldg(&g_rowstart[2 * N_NODES + n + 1]);

    const char* hb = reinterpret_cast<const char*>(g_hh);
    const size_t relstride = (size_t)M_PAD * OUT_C * 2;

    float4 acc = make_float4(0.f, 0.f, 0.f, 0.f);
    accum_segment(acc, e0, f0, hb,                 lane);
    accum_segment(acc, e1, f1, hb + relstride,     lane);
    accum_segment(acc, e2, f2, hb + 2 * relstride, lane);

    acc.x = fmaxf(acc.x, 0.f); acc.y = fmaxf(acc.y, 0.f);
    acc.z = fmaxf(acc.z, 0.f); acc.w = fmaxf(acc.w, 0.f);
    out4[(size_t)n * (OUT_C / 4) + lane] = acc;
}

// ---------------------------------------------------------------------------
// launch
// ---------------------------------------------------------------------------
extern "C" void kernel_launch(void* const* d_in, const int* in_sizes, int n_in,
                              void* d_out, int out_size) {
    const float* x  = (const float*)d_in[0];
    const float* W0 = (const float*)d_in[1];
    const float* W1 = (const float*)d_in[2];
    const float* W2 = (const float*)d_in[3];
    const int* s0 = (const int*)d_in[4];
    const int* d0 = (const int*)d_in[5];
    const int* s1 = (const int*)d_in[6];
    const int* d1 = (const int*)d_in[7];
    const int* s2 = (const int*)d_in[8];
    const int* d2 = (const int*)d_in[9];
    float* out = (float*)d_out;

    // CSR build
    count_kernel<<<(3 * E4 + 255) / 256, 256>>>(d0, d1, d2);
    scan_a_kernel<<<SCAN_BLOCKS, 256>>>();
    scan_c_kernel<<<SCAN_BLOCKS, 256>>>();
    fill_kernel<<<(3 * E4 + 255) / 256, 256>>>(s0, d0, s1, d1, s2, d2);

    // GEMM: h_r = x @ W_r (fp16 HMMA, fp16 output)
    {
        static bool attr_set = false;   // idempotent attribute set
        if (!attr_set) {
            cudaFuncSetAttribute(gemm_hmma_kernel,
                                 cudaFuncAttributeMaxDynamicSharedMemorySize,
                                 SMEM_BYTES);
            attr_set = true;
        }
        gemm_hmma_kernel<<<N_TILES, 256, SMEM_BYTES>>>(
            reinterpret_cast<const float4*>(x), W0, W1, W2);
    }

    // Gather + relu (fused, one warp per node)
    {
        long long threads = (long long)N_NODES * 32;
        int blocks = (int)((threads + 255) / 256);
        gather_kernel<<<blocks, 256>>>(reinterpret_cast<float4*>(out));
    }
}

// round 13
// speedup vs baseline: 1.6464x; 1.0331x over previous
#include <cuda_runtime.h>
#include <cuda_fp16.h>
#include <cstdint>

#define N_NODES 100000
#define N_EDGES 600000
#define IN_C    128
#define OUT_C   128
#define M_TILE  128
#define N_TILES ((N_NODES + M_TILE - 1) / M_TILE)   // 782
#define M_PAD   (N_TILES * M_TILE)                  // 100096

#define AH_STRIDE 136
#define BH_STRIDE 136
#define A_BYTES   (M_TILE * AH_STRIDE * 2)           // 34816
#define B_BYTES   (IN_C  * BH_STRIDE * 2)            // 34816
#define SMEM_BYTES (A_BYTES + B_BYTES)               // 69632

#define NB      (3 * N_NODES)
#define SCAN_BS 2048
#define SCAN_BLOCKS ((NB + SCAN_BS - 1) / SCAN_BS)   // 147

// h[r][M_PAD][128] in fp16
__device__ __half2 g_hh[(size_t)3 * M_PAD * (OUT_C / 2)];
// CSR infrastructure (g_cnt zeroed at load; re-zeroed by scan_c every run)
__device__ int g_cnt[NB];
__device__ int g_rowstart[NB + 1];
__device__ int g_cursor[NB];
__device__ int g_sorted[3 * N_EDGES];
__device__ int g_partial[SCAN_BLOCKS];

// ---------------------------------------------------------------------------
// 1) GEMM: h_j = x @ W_j via mma.sync.m16n8k16.f16 + ldmatrix (unchanged R12)
// ---------------------------------------------------------------------------
__global__ __launch_bounds__(256, 2) void gemm_hmma_kernel(
        const float4* __restrict__ x4,
        const float* __restrict__ W0,
        const float* __restrict__ W1,
        const float* __restrict__ W2) {
    extern __shared__ char smem[];
    char* As = smem;
    char* Bs = smem + A_BYTES;

    int tid  = threadIdx.x;
    int lane = tid & 31;
    int wid  = tid >> 5;
    int wr   = wid >> 2;
    int wc   = wid & 3;
    int g    = lane >> 2;
    int tg   = lane & 3;

    int tile_row0 = blockIdx.x * M_TILE;

    uint32_t As_u = (uint32_t)__cvta_generic_to_shared(As);
    uint32_t Bs_u = (uint32_t)__cvta_generic_to_shared(Bs);

    #pragma unroll
    for (int i = tid; i < 4096; i += 256) {
        int row = i >> 5, c4 = i & 31;
        int srow = tile_row0 + row;
        if (srow >= N_NODES) srow = 0;
        float4 v = __ldg(x4 + (size_t)srow * (IN_C / 4) + c4);
        __half2 h0 = __floats2half2_rn(v.x, v.y);
        __half2 h1 = __floats2half2_rn(v.z, v.w);
        uint2 u = { *reinterpret_cast<uint32_t*>(&h0),
                    *reinterpret_cast<uint32_t*>(&h1) };
        *reinterpret_cast<uint2*>(As + row * (AH_STRIDE * 2) + c4 * 8) = u;
    }

    for (int rel = 0; rel < 3; rel++) {
        const float* Wj = (rel == 0) ? W0 : (rel == 1 ? W1 : W2);
        __half2* hj = g_hh + (size_t)rel * M_PAD * (OUT_C / 2);

        __syncthreads();
        #pragma unroll
        for (int i = tid; i < 4096; i += 256) {
            int k = i >> 5, n4 = i & 31;
            float4 v = __ldg(reinterpret_cast<const float4*>(
                             Wj + (size_t)k * OUT_C) + n4);
            __half2 h0 = __floats2half2_rn(v.x, v.y);
            __half2 h1 = __floats2half2_rn(v.z, v.w);
            uint2 u = { *reinterpret_cast<uint32_t*>(&h0),
                        *reinterpret_cast<uint32_t*>(&h1) };
        *reinterpret_cast<uint2*>(Bs + k * (BH_STRIDE * 2) + n4 * 8) = u;
        }
        __syncthreads();

        float acc[4][4][4];
        #pragma unroll
        for (int mt = 0; mt < 4; mt++)
            #pragma unroll
            for (int nt = 0; nt < 4; nt++)
                #pragma unroll
                for (int r = 0; r < 4; r++) acc[mt][nt][r] = 0.f;

        #pragma unroll
        for (int ks = 0; ks < IN_C / 16; ks++) {
            uint32_t a[4][4], b[4][2];
            #pragma unroll
            for (int mt = 0; mt < 4; mt++) {
                int arow = wr * 64 + mt * 16 + (lane & 15);
                uint32_t addr = As_u + arow * (AH_STRIDE * 2)
                              + ks * 32 + ((lane >> 4) * 16);
                asm volatile(
                    "ldmatrix.sync.aligned.m8n8.x4.shared.b16 {%0,%1,%2,%3}, [%4];"
                    : "=r"(a[mt][0]), "=r"(a[mt][1]),
                      "=r"(a[mt][2]), "=r"(a[mt][3])
                    : "r"(addr));
            }
            #pragma unroll
            for (int nt = 0; nt < 4; nt++) {
                int brow = ks * 16 + (lane & 15);
                uint32_t addr = Bs_u + brow * (BH_STRIDE * 2)
                              + (wc * 32 + nt * 8) * 2;
                asm volatile(
                    "ldmatrix.sync.aligned.m8n8.x2.trans.shared.b16 {%0,%1}, [%2];"
                    : "=r"(b[nt][0]), "=r"(b[nt][1])
                    : "r"(addr));
            }
            #pragma unroll
            for (int mt = 0; mt < 4; mt++)
                #pragma unroll
                for (int nt = 0; nt < 4; nt++) {
                    asm volatile(
                        "mma.sync.aligned.m16n8k16.row.col.f32.f16.f16.f32 "
                        "{%0,%1,%2,%3}, {%4,%5,%6,%7}, {%8,%9}, {%0,%1,%2,%3};"
                        : "+f"(acc[mt][nt][0]), "+f"(acc[mt][nt][1]),
                          "+f"(acc[mt][nt][2]), "+f"(acc[mt][nt][3])
                        : "r"(a[mt][0]), "r"(a[mt][1]),
                          "r"(a[mt][2]), "r"(a[mt][3]),
                          "r"(b[nt][0]), "r"(b[nt][1]));
                }
        }

        #pragma unroll
        for (int mt = 0; mt < 4; mt++) {
            int row = tile_row0 + wr * 64 + mt * 16 + g;
            #pragma unroll
            for (int nt = 0; nt < 4; nt++) {
                int col = wc * 32 + nt * 8 + 2 * tg;
                hj[(size_t)row * (OUT_C / 2) + col / 2] =
                    __floats2half2_rn(acc[mt][nt][0], acc[mt][nt][1]);
                hj[(size_t)(row + 8) * (OUT_C / 2) + col / 2] =
                    __floats2half2_rn(acc[mt][nt][2], acc[mt][nt][3]);
            }
        }
    }
}

// ---------------------------------------------------------------------------
// CSR build: count (x8) -> scan_a -> scan_c -> fill (x8)
// ---------------------------------------------------------------------------
#define E8 (N_EDGES / 8)   // 75000

__global__ void count_kernel(const int* __restrict__ d0,
                             const int* __restrict__ d1,
                             const int* __restrict__ d2) {
    unsigned gid = blockIdx.x * blockDim.x + threadIdx.x;
    if (gid >= 3u * E8) return;
    int rel = gid / E8;
    int e8  = gid % E8;
    const int* dp = (rel == 0) ? d0 : (rel == 1 ? d1 : d2);
    int4 da = __ldg(reinterpret_cast<const int4*>(dp) + e8 * 2);
    int4 db = __ldg(reinterpret_cast<const int4*>(dp) + e8 * 2 + 1);
    int* base = g_cnt + rel * N_NODES;
    atomicAdd(base + da.x, 1); atomicAdd(base + da.y, 1);
    atomicAdd(base + da.z, 1); atomicAdd(base + da.w, 1);
    atomicAdd(base + db.x, 1); atomicAdd(base + db.y, 1);
    atomicAdd(base + db.z, 1); atomicAdd(base + db.w, 1);
}

__global__ void scan_a_kernel() {
    __shared__ int sb[256];
    int t = threadIdx.x;
    int base = blockIdx.x * SCAN_BS + t * 8;
    int sum = 0;
    #pragma unroll
    for (int j = 0; j < 8; j++) {
        int idx = base + j;
        if (idx < NB) sum += g_cnt[idx];
    }
    sb[t] = sum;
    __syncthreads();
    for (int off = 128; off > 0; off >>= 1) {
        if (t < off) sb[t] += sb[t + off];
        __syncthreads();
    }
    if (t == 0) g_partial[blockIdx.x] = sb[0];
}

__global__ void scan_c_kernel() {
    __shared__ int sb[256];
    __shared__ int base_sh;
    int t = threadIdx.x;

    int p = (t < (int)blockIdx.x) ? g_partial[t] : 0;
    sb[t] = p;
    __syncthreads();
    for (int off = 128; off > 0; off >>= 1) {
        if (t < off) sb[t] += sb[t + off];
        __syncthreads();
    }
    if (t == 0) base_sh = sb[0];
    __syncthreads();

    int base = blockIdx.x * SCAN_BS + t * 8;
    int v[8];
    int tsum = 0;
    #pragma unroll
    for (int j = 0; j < 8; j++) {
        int idx = base + j;
        v[j] = (idx < NB) ? g_cnt[idx] : 0;
        if (idx < NB) g_cnt[idx] = 0;
        tsum += v[j];
    }
    sb[t] = tsum;
    __syncthreads();
    for (int off = 1; off < 256; off <<= 1) {
        int add = (t >= off) ? sb[t - off] : 0;
        __syncthreads();
        sb[t] += add;
        __syncthreads();
    }
    int run = base_sh + sb[t] - tsum;
    #pragma unroll
    for (int j = 0; j < 8; j++) {
        int idx = base + j;
        if (idx < NB) {
            g_rowstart[idx] = run;
            g_cursor[idx] = run;
            run += v[j];
        }
    }
    if (blockIdx.x == 0 && t == 0) g_rowstart[NB] = 3 * N_EDGES;
}

__global__ void fill_kernel(const int* __restrict__ s0, const int* __restrict__ d0,
                            const int* __restrict__ s1, const int* __restrict__ d1,
                            const int* __restrict__ s2, const int* __restrict__ d2) {
    unsigned gid = blockIdx.x * blockDim.x + threadIdx.x;
    if (gid >= 3u * E8) return;
    int rel = gid / E8;
    int e8  = gid % E8;
    const int* sp = (rel == 0) ? s0 : (rel == 1 ? s1 : s2);
    const int* dp = (rel == 0) ? d0 : (rel == 1 ? d1 : d2);
    int4 sa = __ldg(reinterpret_cast<const int4*>(sp) + e8 * 2);
    int4 sb = __ldg(reinterpret_cast<const int4*>(sp) + e8 * 2 + 1);
    int4 da = __ldg(reinterpret_cast<const int4*>(dp) + e8 * 2);
    int4 db = __ldg(reinterpret_cast<const int4*>(dp) + e8 * 2 + 1);
    int* cur = g_cursor + rel * N_NODES;
    g_sorted[atomicAdd(cur + da.x, 1)] = sa.x;
    g_sorted[atomicAdd(cur + da.y, 1)] = sa.y;
    g_sorted[atomicAdd(cur + da.z, 1)] = sa.z;
    g_sorted[atomicAdd(cur + da.w, 1)] = sa.w;
    g_sorted[atomicAdd(cur + db.x, 1)] = sb.x;
    g_sorted[atomicAdd(cur + db.y, 1)] = sb.y;
    g_sorted[atomicAdd(cur + db.z, 1)] = sb.z;
    g_sorted[atomicAdd(cur + db.w, 1)] = sb.w;
}

// ---------------------------------------------------------------------------
// Gather (fused 3 relations, fp16 h rows): one warp per node (unchanged)
// ---------------------------------------------------------------------------
static __device__ __forceinline__ void accum_segment(
        float4& acc, int e, int end, const char* hb, int lane) {
    for (; e + 3 < end; e += 4) {
        int s0 = __ldg(&g_sorted[e]);
        int s1 = __ldg(&g_sorted[e + 1]);
        int s2 = __ldg(&g_sorted[e + 2]);
        int s3 = __ldg(&g_sorted[e + 3]);
        uint2 u0 = __ldg(reinterpret_cast<const uint2*>(hb + (size_t)s0 * 256 + lane * 8));
        uint2 u1 = __ldg(reinterpret_cast<const uint2*>(hb + (size_t)s1 * 256 + lane * 8));
        uint2 u2 = __ldg(reinterpret_cast<const uint2*>(hb + (size_t)s2 * 256 + lane * 8));
        uint2 u3 = __ldg(reinterpret_cast<const uint2*>(hb + (size_t)s3 * 256 + lane * 8));
        #pragma unroll
        for (int j = 0; j < 4; j++) {
            uint2 u = (j == 0) ? u0 : (j == 1) ? u1 : (j == 2) ? u2 : u3;
            float2 f0 = __half22float2(*reinterpret_cast<__half2*>(&u.x));
            float2 f1 = __half22float2(*reinterpret_cast<__half2*>(&u.y));
            acc.x += f0.x; acc.y += f0.y; acc.z += f1.x; acc.w += f1.y;
        }
    }
    for (; e < end; e++) {
        int s0 = __ldg(&g_sorted[e]);
        uint2 u = __ldg(reinterpret_cast<const uint2*>(hb + (size_t)s0 * 256 + lane * 8));
        float2 f0 = __half22float2(*reinterpret_cast<__half2*>(&u.x));
        float2 f1 = __half22float2(*reinterpret_cast<__half2*>(&u.y));
        acc.x += f0.x; acc.y += f0.y; acc.z += f1.x; acc.w += f1.y;
    }
}

__global__ void gather_kernel(float4* __restrict__ out4) {
    unsigned n    = (blockIdx.x * blockDim.x + threadIdx.x) >> 5;
    int      lane = threadIdx.x & 31;
    if (n >= (unsigned)N_NODES) return;

    int e0 = __ldg(&g_rowstart[n]);
    int f0 = __ldg(&g_rowstart[n + 1]);
    int e1 = __ldg(&g_rowstart[N_NODES + n]);
    int f1 = __ldg(&g_rowstart[N_NODES + n + 1]);
    int e2 = __ldg(&g_rowstart[2 * N_NODES + n]);
    int f2 = __ldg(&g_rowstart[2 * N_NODES + n + 1]);

    const char* hb = reinterpret_cast<const char*>(g_hh);
    const size_t relstride = (size_t)M_PAD * OUT_C * 2;

    float4 acc = make_float4(0.f, 0.f, 0.f, 0.f);
    accum_segment(acc, e0, f0, hb,                 lane);
    accum_segment(acc, e1, f1, hb + relstride,     lane);
    accum_segment(acc, e2, f2, hb + 2 * relstride, lane);

    acc.x = fmaxf(acc.x, 0.f); acc.y = fmaxf(acc.y, 0.f);
    acc.z = fmaxf(acc.z, 0.f); acc.w = fmaxf(acc.w, 0.f);
    out4[(size_t)n * (OUT_C / 4) + lane] = acc;
}

// ---------------------------------------------------------------------------
// launch: CSR build on a side stream, GEMM on the main stream, join, gather.
// Stream/event handles are created lazily OUTSIDE capture (first correctness
// call) and reused — same idempotent-handle pattern as attr_set.
// ---------------------------------------------------------------------------
extern "C" void kernel_launch(void* const* d_in, const int* in_sizes, int n_in,
                              void* d_out, int out_size) {
    const float* x  = (const float*)d_in[0];
    const float* W0 = (const float*)d_in[1];
    const float* W1 = (const float*)d_in[2];
    const float* W2 = (const float*)d_in[3];
    const int* s0 = (const int*)d_in[4];
    const int* d0 = (const int*)d_in[5];
    const int* s1 = (const int*)d_in[6];
    const int* d1 = (const int*)d_in[7];
    const int* s2 = (const int*)d_in[8];
    const int* d2 = (const int*)d_in[9];
    float* out = (float*)d_out;

    static cudaStream_t s_side = nullptr;
    static cudaEvent_t  ev_fork = nullptr, ev_join = nullptr;
    static bool init_done = false;
    if (!init_done) {
        cudaStreamCreateWithFlags(&s_side, cudaStreamNonBlocking);
        cudaEventCreateWithFlags(&ev_fork, cudaEventDisableTiming);
        cudaEventCreateWithFlags(&ev_join, cudaEventDisableTiming);
        cudaFuncSetAttribute(gemm_hmma_kernel,
                             cudaFuncAttributeMaxDynamicSharedMemorySize,
                             SMEM_BYTES);
        init_done = true;
    }

    // fork: side stream inherits capture via the event edge
    cudaEventRecord(ev_fork, 0);
    cudaStreamWaitEvent(s_side, ev_fork, 0);

    // CSR build on side stream
    count_kernel<<<(3 * E8 + 255) / 256, 256, 0, s_side>>>(d0, d1, d2);
    scan_a_kernel<<<SCAN_BLOCKS, 256, 0, s_side>>>();
    scan_c_kernel<<<SCAN_BLOCKS, 256, 0, s_side>>>();
    fill_kernel<<<(3 * E8 + 255) / 256, 256, 0, s_side>>>(s0, d0, s1, d1, s2, d2);
    cudaEventRecord(ev_join, s_side);

    // GEMM on main stream (overlaps CSR build)
    gemm_hmma_kernel<<<N_TILES, 256, SMEM_BYTES>>>(
        reinterpret_cast<const float4*>(x), W0, W1, W2);

    // join, then gather
    cudaStreamWaitEvent(0, ev_join, 0);
    {
        long long threads = (long long)N_NODES * 32;
        int blocks = (int)((threads + 255) / 256);
        gather_kernel<<<blocks, 256>>>(reinterpret_cast<float4*>(out));
    }
}

// round 14
// speedup vs baseline: 1.8415x; 1.1185x over previous
#include <cuda_runtime.h>
#include <cuda_fp16.h>
#include <cstdint>

#define N_NODES 100000
#define N_EDGES 600000
#define IN_C    128
#define OUT_C   128
#define M_TILE  128
#define N_TILES ((N_NODES + M_TILE - 1) / M_TILE)   // 782
#define M_PAD   (N_TILES * M_TILE)                  // 100096

#define AH_STRIDE 136
#define BH_STRIDE 136
#define A_BYTES   (M_TILE * AH_STRIDE * 2)           // 34816
#define B_BYTES   (IN_C  * BH_STRIDE * 2)            // 34816
#define SMEM_BYTES (A_BYTES + B_BYTES)               // 69632

#define NB      N_NODES                               // dst-only buckets
#define SCAN_BS 2048
#define SCAN_BLOCKS ((NB + SCAN_BS - 1) / SCAN_BS)   // 49

// h[r][M_PAD][128] in fp16 (flat row id = rel*M_PAD + src)
__device__ __half2 g_hh[(size_t)3 * M_PAD * (OUT_C / 2)];
// CSR (g_cnt zeroed at load; re-zeroed by scan_c every run)
__device__ int g_cnt[NB];
__device__ int g_rowstart[NB + 1];
__device__ int g_cursor[NB];
__device__ int g_sorted[3 * N_EDGES];                // packed h-row ids
__device__ int g_partial[SCAN_BLOCKS];

// ---------------------------------------------------------------------------
// 1) GEMM: h_j = x @ W_j via mma.sync.m16n8k16.f16 + ldmatrix (unchanged)
// ---------------------------------------------------------------------------
__global__ __launch_bounds__(256, 2) void gemm_hmma_kernel(
        const float4* __restrict__ x4,
        const float* __restrict__ W0,
        const float* __restrict__ W1,
        const float* __restrict__ W2) {
    extern __shared__ char smem[];
    char* As = smem;
    char* Bs = smem + A_BYTES;

    int tid  = threadIdx.x;
    int lane = tid & 31;
    int wid  = tid >> 5;
    int wr   = wid >> 2;
    int wc   = wid & 3;
    int g    = lane >> 2;
    int tg   = lane & 3;

    int tile_row0 = blockIdx.x * M_TILE;

    uint32_t As_u = (uint32_t)__cvta_generic_to_shared(As);
    uint32_t Bs_u = (uint32_t)__cvta_generic_to_shared(Bs);

    #pragma unroll
    for (int i = tid; i < 4096; i += 256) {
        int row = i >> 5, c4 = i & 31;
        int srow = tile_row0 + row;
        if (srow >= N_NODES) srow = 0;
        float4 v = __ldg(x4 + (size_t)srow * (IN_C / 4) + c4);
        __half2 h0 = __floats2half2_rn(v.x, v.y);
        __half2 h1 = __floats2half2_rn(v.z, v.w);
        uint2 u = { *reinterpret_cast<uint32_t*>(&h0),
                    *reinterpret_cast<uint32_t*>(&h1) };
        *reinterpret_cast<uint2*>(As + row * (AH_STRIDE * 2) + c4 * 8) = u;
    }

    for (int rel = 0; rel < 3; rel++) {
        const float* Wj = (rel == 0) ? W0 : (rel == 1 ? W1 : W2);
        __half2* hj = g_hh + (size_t)rel * M_PAD * (OUT_C / 2);

        __syncthreads();
        #pragma unroll
        for (int i = tid; i < 4096; i += 256) {
            int k = i >> 5, n4 = i & 31;
            float4 v = __ldg(reinterpret_cast<const float4*>(
                             Wj + (size_t)k * OUT_C) + n4);
            __half2 h0 = __floats2half2_rn(v.x, v.y);
            __half2 h1 = __floats2half2_rn(v.z, v.w);
            uint2 u = { *reinterpret_cast<uint32_t*>(&h0),
                        *reinterpret_cast<uint32_t*>(&h1) };
            *reinterpret_cast<uint2*>(Bs + k * (BH_STRIDE * 2) + n4 * 8) = u;
        }
        __syncthreads();

        float acc[4][4][4];
        #pragma unroll
        for (int mt = 0; mt < 4; mt++)
            #pragma unroll
            for (int nt = 0; nt < 4; nt++)
                #pragma unroll
                for (int r = 0; r < 4; r++) acc[mt][nt][r] = 0.f;

        #pragma unroll
        for (int ks = 0; ks < IN_C / 16; ks++) {
            uint32_t a[4][4], b[4][2];
            #pragma unroll
            for (int mt = 0; mt < 4; mt++) {
                int arow = wr * 64 + mt * 16 + (lane & 15);
                uint32_t addr = As_u + arow * (AH_STRIDE * 2)
                              + ks * 32 + ((lane >> 4) * 16);
                asm volatile(
                    "ldmatrix.sync.aligned.m8n8.x4.shared.b16 {%0,%1,%2,%3}, [%4];"
                    : "=r"(a[mt][0]), "=r"(a[mt][1]),
                      "=r"(a[mt][2]), "=r"(a[mt][3])
                    : "r"(addr));
            }
            #pragma unroll
            for (int nt = 0; nt < 4; nt++) {
                int brow = ks * 16 + (lane & 15);
                uint32_t addr = Bs_u + brow * (BH_STRIDE * 2)
                              + (wc * 32 + nt * 8) * 2;
                asm volatile(
                    "ldmatrix.sync.aligned.m8n8.x2.trans.shared.b16 {%0,%1}, [%2];"
                    : "=r"(b[nt][0]), "=r"(b[nt][1])
                    : "r"(addr));
            }
            #pragma unroll
            for (int mt = 0; mt < 4; mt++)
                #pragma unroll
                for (int nt = 0; nt < 4; nt++) {
                    asm volatile(
                        "mma.sync.aligned.m16n8k16.row.col.f32.f16.f16.f32 "
                        "{%0,%1,%2,%3}, {%4,%5,%6,%7}, {%8,%9}, {%0,%1,%2,%3};"
                        : "+f"(acc[mt][nt][0]), "+f"(acc[mt][nt][1]),
                          "+f"(acc[mt][nt][2]), "+f"(acc[mt][nt][3])
                        : "r"(a[mt][0]), "r"(a[mt][1]),
                          "r"(a[mt][2]), "r"(a[mt][3]),
                          "r"(b[nt][0]), "r"(b[nt][1]));
                }
        }

        #pragma unroll
        for (int mt = 0; mt < 4; mt++) {
            int row = tile_row0 + wr * 64 + mt * 16 + g;
            #pragma unroll
            for (int nt = 0; nt < 4; nt++) {
                int col = wc * 32 + nt * 8 + 2 * tg;
                hj[(size_t)row * (OUT_C / 2) + col / 2] =
                    __floats2half2_rn(acc[mt][nt][0], acc[mt][nt][1]);
                hj[(size_t)(row + 8) * (OUT_C / 2) + col / 2] =
                    __floats2half2_rn(acc[mt][nt][2], acc[mt][nt][3]);
            }
        }
    }
}

// ---------------------------------------------------------------------------
// CSR build (dst-only buckets): count (x8) -> scan_a -> scan_c -> fill (x8)
// ---------------------------------------------------------------------------
#define E8 (N_EDGES / 8)   // 75000

__global__ void count_kernel(const int* __restrict__ d0,
                             const int* __restrict__ d1,
                             const int* __restrict__ d2) {
    unsigned gid = blockIdx.x * blockDim.x + threadIdx.x;
    if (gid >= 3u * E8) return;
    int rel = gid / E8;
    int e8  = gid % E8;
    const int* dp = (rel == 0) ? d0 : (rel == 1 ? d1 : d2);
    int4 da = __ldg(reinterpret_cast<const int4*>(dp) + e8 * 2);
    int4 db = __ldg(reinterpret_cast<const int4*>(dp) + e8 * 2 + 1);
    atomicAdd(g_cnt + da.x, 1); atomicAdd(g_cnt + da.y, 1);
    atomicAdd(g_cnt + da.z, 1); atomicAdd(g_cnt + da.w, 1);
    atomicAdd(g_cnt + db.x, 1); atomicAdd(g_cnt + db.y, 1);
    atomicAdd(g_cnt + db.z, 1); atomicAdd(g_cnt + db.w, 1);
}

__global__ void scan_a_kernel() {
    __shared__ int sb[256];
    int t = threadIdx.x;
    int base = blockIdx.x * SCAN_BS + t * 8;
    int sum = 0;
    #pragma unroll
    for (int j = 0; j < 8; j++) {
        int idx = base + j;
        if (idx < NB) sum += g_cnt[idx];
    }
    sb[t] = sum;
    __syncthreads();
    for (int off = 128; off > 0; off >>= 1) {
        if (t < off) sb[t] += sb[t + off];
        __syncthreads();
    }
    if (t == 0) g_partial[blockIdx.x] = sb[0];
}

__global__ void scan_c_kernel() {
    __shared__ int sb[256];
    __shared__ int base_sh;
    int t = threadIdx.x;

    int p = (t < (int)blockIdx.x && t < SCAN_BLOCKS) ? g_partial[t] : 0;
    sb[t] = p;
    __syncthreads();
    for (int off = 128; off > 0; off >>= 1) {
        if (t < off) sb[t] += sb[t + off];
        __syncthreads();
    }
    if (t == 0) base_sh = sb[0];
    __syncthreads();

    int base = blockIdx.x * SCAN_BS + t * 8;
    int v[8];
    int tsum = 0;
    #pragma unroll
    for (int j = 0; j < 8; j++) {
        int idx = base + j;
        v[j] = (idx < NB) ? g_cnt[idx] : 0;
        if (idx < NB) g_cnt[idx] = 0;          // re-zero for next run
        tsum += v[j];
    }
    sb[t] = tsum;
    __syncthreads();
    for (int off = 1; off < 256; off <<= 1) {
        int add = (t >= off) ? sb[t - off] : 0;
        __syncthreads();
        sb[t] += add;
        __syncthreads();
    }
    int run = base_sh + sb[t] - tsum;
    #pragma unroll
    for (int j = 0; j < 8; j++) {
        int idx = base + j;
        if (idx < NB) {
            g_rowstart[idx] = run;
            g_cursor[idx] = run;
            run += v[j];
        }
    }
    if (blockIdx.x == 0 && t == 0) g_rowstart[NB] = 3 * N_EDGES;
}

__global__ void fill_kernel(const int* __restrict__ s0, const int* __restrict__ d0,
                            const int* __restrict__ s1, const int* __restrict__ d1,
                            const int* __restrict__ s2, const int* __restrict__ d2) {
    unsigned gid = blockIdx.x * blockDim.x + threadIdx.x;
    if (gid >= 3u * E8) return;
    int rel = gid / E8;
    int e8  = gid % E8;
    const int* sp = (rel == 0) ? s0 : (rel == 1 ? s1 : s2);
    const int* dp = (rel == 0) ? d0 : (rel == 1 ? d1 : d2);
    int4 sa = __ldg(reinterpret_cast<const int4*>(sp) + e8 * 2);
    int4 sb = __ldg(reinterpret_cast<const int4*>(sp) + e8 * 2 + 1);
    int4 da = __ldg(reinterpret_cast<const int4*>(dp) + e8 * 2);
    int4 db = __ldg(reinterpret_cast<const int4*>(dp) + e8 * 2 + 1);
    int rbase = rel * M_PAD;                    // packed h-row id offset
    g_sorted[atomicAdd(g_cnt + 0 + da.x, 0) * 0 + atomicAdd(g_cursor + da.x, 1)] = rbase + sa.x;
    g_sorted[atomicAdd(g_cursor + da.y, 1)] = rbase + sa.y;
    g_sorted[atomicAdd(g_cursor + da.z, 1)] = rbase + sa.z;
    g_sorted[atomicAdd(g_cursor + da.w, 1)] = rbase + sa.w;
    g_sorted[atomicAdd(g_cursor + db.x, 1)] = rbase + sb.x;
    g_sorted[atomicAdd(g_cursor + db.y, 1)] = rbase + sb.y;
    g_sorted[atomicAdd(g_cursor + db.z, 1)] = rbase + sb.z;
    g_sorted[atomicAdd(g_cursor + db.w, 1)] = rbase + sb.w;
}

// ---------------------------------------------------------------------------
// Gather: one warp per node, ONE segment (all relations), 8-wide unroll.
// ---------------------------------------------------------------------------
__global__ void gather_kernel(float4* __restrict__ out4) {
    unsigned n    = (blockIdx.x * blockDim.x + threadIdx.x) >> 5;
    int      lane = threadIdx.x & 31;
    if (n >= (unsigned)N_NODES) return;

    int e   = __ldg(&g_rowstart[n]);
    int end = __ldg(&g_rowstart[n + 1]);

    const char* hb = reinterpret_cast<const char*>(g_hh);
    float4 acc = make_float4(0.f, 0.f, 0.f, 0.f);

    for (; e + 7 < end; e += 8) {
        int r[8];
        #pragma unroll
        for (int j = 0; j < 8; j++) r[j] = __ldg(&g_sorted[e + j]);
        uint2 u[8];
        #pragma unroll
        for (int j = 0; j < 8; j++)
            u[j] = __ldg(reinterpret_cast<const uint2*>(
                         hb + (size_t)r[j] * 256 + lane * 8));
        #pragma unroll
        for (int j = 0; j < 8; j++) {
            float2 f0 = __half22float2(*reinterpret_cast<__half2*>(&u[j].x));
            float2 f1 = __half22float2(*reinterpret_cast<__half2*>(&u[j].y));
            acc.x += f0.x; acc.y += f0.y; acc.z += f1.x; acc.w += f1.y;
        }
    }
    for (; e + 1 < end; e += 2) {
        int r0 = __ldg(&g_sorted[e]);
        int r1 = __ldg(&g_sorted[e + 1]);
        uint2 u0 = __ldg(reinterpret_cast<const uint2*>(hb + (size_t)r0 * 256 + lane * 8));
        uint2 u1 = __ldg(reinterpret_cast<const uint2*>(hb + (size_t)r1 * 256 + lane * 8));
        float2 a0 = __half22float2(*reinterpret_cast<__half2*>(&u0.x));
        float2 a1 = __half22float2(*reinterpret_cast<__half2*>(&u0.y));
        float2 b0 = __half22float2(*reinterpret_cast<__half2*>(&u1.x));
        float2 b1 = __half22float2(*reinterpret_cast<__half2*>(&u1.y));
        acc.x += a0.x + b0.x; acc.y += a0.y + b0.y;
        acc.z += a1.x + b1.x; acc.w += a1.y + b1.y;
    }
    if (e < end) {
        int r0 = __ldg(&g_sorted[e]);
        uint2 u = __ldg(reinterpret_cast<const uint2*>(hb + (size_t)r0 * 256 + lane * 8));
        float2 f0 = __half22float2(*reinterpret_cast<__half2*>(&u.x));
        float2 f1 = __half22float2(*reinterpret_cast<__half2*>(&u.y));
        acc.x += f0.x; acc.y += f0.y; acc.z += f1.x; acc.w += f1.y;
    }

    acc.x = fmaxf(acc.x, 0.f); acc.y = fmaxf(acc.y, 0.f);
    acc.z = fmaxf(acc.z, 0.f); acc.w = fmaxf(acc.w, 0.f);
    out4[(size_t)n * (OUT_C / 4) + lane] = acc;
}

// ---------------------------------------------------------------------------
// launch: CSR on side stream || GEMM on main stream, join, gather.
// ---------------------------------------------------------------------------
extern "C" void kernel_launch(void* const* d_in, const int* in_sizes, int n_in,
                              void* d_out, int out_size) {
    const float* x  = (const float*)d_in[0];
    const float* W0 = (const float*)d_in[1];
    const float* W1 = (const float*)d_in[2];
    const float* W2 = (const float*)d_in[3];
    const int* s0 = (const int*)d_in[4];
    const int* d0 = (const int*)d_in[5];
    const int* s1 = (const int*)d_in[6];
    const int* d1 = (const int*)d_in[7];
    const int* s2 = (const int*)d_in[8];
    const int* d2 = (const int*)d_in[9];
    float* out = (float*)d_out;

    static cudaStream_t s_side = nullptr;
    static cudaEvent_t  ev_fork = nullptr, ev_join = nullptr;
    static bool init_done = false;
    if (!init_done) {
        cudaStreamCreateWithFlags(&s_side, cudaStreamNonBlocking);
        cudaEventCreateWithFlags(&ev_fork, cudaEventDisableTiming);
        cudaEventCreateWithFlags(&ev_join, cudaEventDisableTiming);
        cudaFuncSetAttribute(gemm_hmma_kernel,
                             cudaFuncAttributeMaxDynamicSharedMemorySize,
                             SMEM_BYTES);
        init_done = true;
    }

    cudaEventRecord(ev_fork, 0);
    cudaStreamWaitEvent(s_side, ev_fork, 0);

    count_kernel<<<(3 * E8 + 255) / 256, 256, 0, s_side>>>(d0, d1, d2);
    scan_a_kernel<<<SCAN_BLOCKS, 256, 0, s_side>>>();
    scan_c_kernel<<<SCAN_BLOCKS, 256, 0, s_side>>>();
    fill_kernel<<<(3 * E8 + 255) / 256, 256, 0, s_side>>>(s0, d0, s1, d1, s2, d2);
    cudaEventRecord(ev_join, s_side);

    gemm_hmma_kernel<<<N_TILES, 256, SMEM_BYTES>>>(
        reinterpret_cast<const float4*>(x), W0, W1, W2);

    cudaStreamWaitEvent(0, ev_join, 0);
    {
        long long threads = (long long)N_NODES * 32;
        int blocks = (int)((threads + 255) / 256);
        gather_kernel<<<blocks, 256>>>(reinterpret_cast<float4*>(out));
    }
}